// round 1
// baseline (speedup 1.0000x reference)
#include <cuda_runtime.h>
#include <cuda_bf16.h>
#include <math.h>

// Problem shapes (fixed):
// x: [8, 1024, 64, 64]  B=8, C=1024, H=W=64, N=4096
// Ci=512, pooled M=1024 (32x32)

#define B_  8
#define C_  1024
#define CI_ 512
#define N_  4096
#define M_  1024

// ---------------- scratch (device globals; allocation-free) ----------------
__device__ float d_px[B_ * C_ * M_];        //  32 MB  pooled x  [B,C,32,32]
__device__ float d_theta[B_ * CI_ * N_];    //  64 MB  [B,Ci,N]
__device__ float d_phi[B_ * CI_ * M_];      //  16 MB  [B,Ci,M]
__device__ float d_g[B_ * CI_ * M_];        //  16 MB  [B,Ci,M]
__device__ float d_p[(size_t)B_ * N_ * M_]; // 128 MB  scores / softmax in-place [B,N,M]
__device__ float d_t[B_ * CI_ * N_];        //  64 MB  [B,Ci,N]
__device__ float d_y[(size_t)B_ * C_ * N_]; // 128 MB  [B,C,N]
__device__ float d_stats[2 * C_];           //  mean, rstd

// ---------------- maxpool 2x2 stride 2 ----------------
__global__ void maxpool_kernel(const float* __restrict__ x, float* __restrict__ px) {
    long long idx = (long long)blockIdx.x * blockDim.x + threadIdx.x; // over B*C*32*32
    if (idx >= (long long)B_ * C_ * 32 * 32) return;
    int j = (int)(idx & 31);
    int i = (int)((idx >> 5) & 31);
    long long bc = idx >> 10;
    const float* xp = x + bc * 4096 + (long long)(i * 2) * 64 + j * 2;
    float v0 = fmaxf(xp[0], xp[1]);
    float v1 = fmaxf(xp[64], xp[65]);
    px[idx] = fmaxf(v0, v1);
}

// ---------------- generic strided batched GEMM ----------------
// C[b][m][n] = bias[m] + sum_k A[b][m][k] * B[b][k][n]
// A element: A + b*a_bs + m*sa_m + k*sa_k
// B element: B + b*b_bs + k*sb_k + n*sb_n
// C row-major [M x N], batch stride c_bs. M = gridDim.y*64, all dims % 64 == 0, K % 16 == 0.
#define BM 64
#define BN 64
#define BK 16

__global__ void gemm64_kernel(const float* __restrict__ A, const float* __restrict__ Bm,
                              const float* __restrict__ bias, float* __restrict__ Cm,
                              int N, int K,
                              long long sa_m, long long sa_k, long long a_bs,
                              long long sb_k, long long sb_n, long long b_bs,
                              long long c_bs) {
    __shared__ float As[BK][BM];
    __shared__ float Bs[BK][BN];

    int b = blockIdx.z;
    const float* Ab = A + (long long)b * a_bs;
    const float* Bb = Bm + (long long)b * b_bs;
    float* Cb = Cm + (long long)b * c_bs;

    int m0 = blockIdx.y * BM;
    int n0 = blockIdx.x * BN;
    int tid = threadIdx.x;           // 256 threads
    int tx = tid & 15;               // 0..15 -> n
    int ty = tid >> 4;               // 0..15 -> m

    float acc[4][4] = {};

    for (int k0 = 0; k0 < K; k0 += BK) {
        #pragma unroll
        for (int i = tid; i < BM * BK; i += 256) {
            int mm = i & (BM - 1);
            int kk = i >> 6;
            As[kk][mm] = Ab[(long long)(m0 + mm) * sa_m + (long long)(k0 + kk) * sa_k];
        }
        #pragma unroll
        for (int i = tid; i < BN * BK; i += 256) {
            int nn = i & (BN - 1);
            int kk = i >> 6;
            Bs[kk][nn] = Bb[(long long)(k0 + kk) * sb_k + (long long)(n0 + nn) * sb_n];
        }
        __syncthreads();

        #pragma unroll
        for (int kk = 0; kk < BK; kk++) {
            float4 a4 = *reinterpret_cast<const float4*>(&As[kk][ty * 4]);
            float4 b4 = *reinterpret_cast<const float4*>(&Bs[kk][tx * 4]);
            float ar[4] = {a4.x, a4.y, a4.z, a4.w};
            float br[4] = {b4.x, b4.y, b4.z, b4.w};
            #pragma unroll
            for (int i = 0; i < 4; i++)
                #pragma unroll
                for (int j = 0; j < 4; j++)
                    acc[i][j] += ar[i] * br[j];
        }
        __syncthreads();
    }

    #pragma unroll
    for (int i = 0; i < 4; i++) {
        int m = m0 + ty * 4 + i;
        float bv = bias ? bias[m] : 0.0f;
        float* crow = Cb + (long long)m * N + n0 + tx * 4;
        float4 o;
        o.x = acc[i][0] + bv;
        o.y = acc[i][1] + bv;
        o.z = acc[i][2] + bv;
        o.w = acc[i][3] + bv;
        *reinterpret_cast<float4*>(crow) = o;
    }
}

// ---------------- softmax over last dim (M=1024), scaled, in-place ----------------
__global__ void softmax_kernel(float* __restrict__ p, float scale) {
    float* row = p + (size_t)blockIdx.x * M_;
    int tid = threadIdx.x; // 256
    float v[4];
    float mx = -1e30f;
    #pragma unroll
    for (int i = 0; i < 4; i++) {
        v[i] = row[tid + 256 * i] * scale;
        mx = fmaxf(mx, v[i]);
    }
    __shared__ float red[8];
    __shared__ float red2[8];
    #pragma unroll
    for (int o = 16; o > 0; o >>= 1) mx = fmaxf(mx, __shfl_xor_sync(0xffffffffu, mx, o));
    if ((tid & 31) == 0) red[tid >> 5] = mx;
    __syncthreads();
    mx = fmaxf(fmaxf(fmaxf(red[0], red[1]), fmaxf(red[2], red[3])),
               fmaxf(fmaxf(red[4], red[5]), fmaxf(red[6], red[7])));

    float s = 0.0f;
    #pragma unroll
    for (int i = 0; i < 4; i++) {
        v[i] = __expf(v[i] - mx);
        s += v[i];
    }
    #pragma unroll
    for (int o = 16; o > 0; o >>= 1) s += __shfl_xor_sync(0xffffffffu, s, o);
    if ((tid & 31) == 0) red2[tid >> 5] = s;
    __syncthreads();
    s = (red2[0] + red2[1]) + (red2[2] + red2[3]) + (red2[4] + red2[5]) + (red2[6] + red2[7]);
    float inv = 1.0f / s;
    #pragma unroll
    for (int i = 0; i < 4; i++) row[tid + 256 * i] = v[i] * inv;
}

// ---------------- BatchNorm statistics (per channel over B*N) ----------------
__global__ void bn_stats_kernel(const float* __restrict__ y, float* __restrict__ stats) {
    int c = blockIdx.x;
    int tid = threadIdx.x; // 256
    double s = 0.0, s2 = 0.0;
    for (int i = tid; i < B_ * N_; i += 256) {
        int b = i >> 12;
        int n = i & (N_ - 1);
        float v = y[((long long)b * C_ + c) * N_ + n];
        s += (double)v;
        s2 += (double)v * (double)v;
    }
    __shared__ double rs[256];
    __shared__ double rs2[256];
    rs[tid] = s; rs2[tid] = s2;
    __syncthreads();
    for (int o = 128; o > 0; o >>= 1) {
        if (tid < o) { rs[tid] += rs[tid + o]; rs2[tid] += rs2[tid + o]; }
        __syncthreads();
    }
    if (tid == 0) {
        double cnt = (double)(B_ * N_);
        double mean = rs[0] / cnt;
        double var = rs2[0] / cnt - mean * mean;
        stats[c] = (float)mean;
        stats[C_ + c] = rsqrtf((float)var + 1e-5f);
    }
}

// ---------------- BN apply + residual ----------------
__global__ void bn_apply_kernel(const float* __restrict__ y, const float* __restrict__ x,
                                const float* __restrict__ stats,
                                const float* __restrict__ gamma, const float* __restrict__ beta,
                                float* __restrict__ out) {
    long long idx = (long long)blockIdx.x * blockDim.x + threadIdx.x;
    if (idx >= (long long)B_ * C_ * N_) return;
    int c = (int)((idx >> 12) & (C_ - 1));
    float m = stats[c];
    float r = stats[C_ + c];
    out[idx] = (y[idx] - m) * r * gamma[c] + beta[c] + x[idx];
}

// ---------------- launch ----------------
extern "C" void kernel_launch(void* const* d_in, const int* in_sizes, int n_in,
                              void* d_out, int out_size) {
    const float* x       = (const float*)d_in[0];
    const float* w_theta = (const float*)d_in[1];
    const float* b_theta = (const float*)d_in[2];
    const float* w_phi   = (const float*)d_in[3];
    const float* b_phi   = (const float*)d_in[4];
    const float* w_g     = (const float*)d_in[5];
    const float* b_g     = (const float*)d_in[6];
    const float* w_out   = (const float*)d_in[7];
    const float* b_out   = (const float*)d_in[8];
    const float* gamma   = (const float*)d_in[9];
    const float* beta    = (const float*)d_in[10];
    float* out = (float*)d_out;

    float *px, *theta, *phi, *g, *p, *t, *y, *stats;
    cudaGetSymbolAddress((void**)&px, d_px);
    cudaGetSymbolAddress((void**)&theta, d_theta);
    cudaGetSymbolAddress((void**)&phi, d_phi);
    cudaGetSymbolAddress((void**)&g, d_g);
    cudaGetSymbolAddress((void**)&p, d_p);
    cudaGetSymbolAddress((void**)&t, d_t);
    cudaGetSymbolAddress((void**)&y, d_y);
    cudaGetSymbolAddress((void**)&stats, d_stats);

    // 1) maxpool: x [B,C,64,64] -> px [B,C,32,32]
    {
        long long total = (long long)B_ * C_ * 32 * 32;
        maxpool_kernel<<<(unsigned)((total + 255) / 256), 256>>>(x, px);
    }

    // 2) theta = w_theta @ x[b]  : M=512, N=4096, K=1024
    gemm64_kernel<<<dim3(N_ / 64, CI_ / 64, B_), 256>>>(
        w_theta, x, b_theta, theta,
        N_, C_,
        /*sa_m*/ C_, /*sa_k*/ 1, /*a_bs*/ 0,
        /*sb_k*/ N_, /*sb_n*/ 1, /*b_bs*/ (long long)C_ * N_,
        /*c_bs*/ (long long)CI_ * N_);

    // 3) phi = w_phi @ px[b] : M=512, N=1024, K=1024
    gemm64_kernel<<<dim3(M_ / 64, CI_ / 64, B_), 256>>>(
        w_phi, px, b_phi, phi,
        M_, C_,
        C_, 1, 0,
        M_, 1, (long long)C_ * M_,
        (long long)CI_ * M_);

    // 4) g = w_g @ px[b] : M=512, N=1024, K=1024
    gemm64_kernel<<<dim3(M_ / 64, CI_ / 64, B_), 256>>>(
        w_g, px, b_g, g,
        M_, C_,
        C_, 1, 0,
        M_, 1, (long long)C_ * M_,
        (long long)CI_ * M_);

    // 5) scores[b][n][m] = sum_c theta[b][c][n] * phi[b][c][m] : M=4096, N=1024, K=512
    gemm64_kernel<<<dim3(M_ / 64, N_ / 64, B_), 256>>>(
        theta, phi, nullptr, p,
        M_, CI_,
        /*sa_m(n)*/ 1, /*sa_k(c)*/ N_, /*a_bs*/ (long long)CI_ * N_,
        /*sb_k(c)*/ M_, /*sb_n(m)*/ 1, /*b_bs*/ (long long)CI_ * M_,
        /*c_bs*/ (long long)N_ * M_);

    // 6) softmax over m, scale = Ci^-0.5
    softmax_kernel<<<B_ * N_, 256>>>(p, rsqrtf((float)CI_));

    // 7) t[b][c][n] = sum_m g[b][c][m] * p[b][n][m] : M=512, N=4096, K=1024
    gemm64_kernel<<<dim3(N_ / 64, CI_ / 64, B_), 256>>>(
        g, p, nullptr, t,
        N_, M_,
        /*sa_m(c)*/ M_, /*sa_k(m)*/ 1, /*a_bs*/ (long long)CI_ * M_,
        /*sb_k(m)*/ 1, /*sb_n(n)*/ M_, /*b_bs*/ (long long)N_ * M_,
        /*c_bs*/ (long long)CI_ * N_);

    // 8) y = w_out @ t[b] : M=1024, N=4096, K=512
    gemm64_kernel<<<dim3(N_ / 64, C_ / 64, B_), 256>>>(
        w_out, t, b_out, y,
        N_, CI_,
        CI_, 1, 0,
        N_, 1, (long long)CI_ * N_,
        (long long)C_ * N_);

    // 9) BN stats per channel
    bn_stats_kernel<<<C_, 256>>>(y, stats);

    // 10) BN apply + residual
    {
        long long total = (long long)B_ * C_ * N_;
        bn_apply_kernel<<<(unsigned)((total + 255) / 256), 256>>>(y, x, stats, gamma, beta, out);
    }
}

// round 3
// speedup vs baseline: 5.0459x; 5.0459x over previous
#include <cuda_runtime.h>
#include <cuda_bf16.h>
#include <cstdint>
#include <math.h>

#define B_  8
#define C_  1024
#define CI_ 512
#define N_  4096
#define M_  1024

// ======================= scratch (device globals) =======================
__device__ __align__(1024) __nv_bfloat16 s_xT_h[(size_t)B_*N_*C_];   // [b][n][c]
__device__ __align__(1024) __nv_bfloat16 s_xT_l[(size_t)B_*N_*C_];
__device__ __align__(1024) __nv_bfloat16 s_pxT_h[(size_t)B_*M_*C_];  // [b][m][c]
__device__ __align__(1024) __nv_bfloat16 s_pxT_l[(size_t)B_*M_*C_];
__device__ __align__(1024) __nv_bfloat16 s_wth_h[CI_*C_], s_wth_l[CI_*C_];
__device__ __align__(1024) __nv_bfloat16 s_wph_h[CI_*C_], s_wph_l[CI_*C_];
__device__ __align__(1024) __nv_bfloat16 s_wg_h[CI_*C_],  s_wg_l[CI_*C_];
__device__ __align__(1024) __nv_bfloat16 s_wo_h[C_*CI_],  s_wo_l[C_*CI_];
__device__ __align__(1024) __nv_bfloat16 s_thT_h[(size_t)B_*N_*CI_], s_thT_l[(size_t)B_*N_*CI_];
__device__ __align__(1024) __nv_bfloat16 s_phT_h[(size_t)B_*M_*CI_], s_phT_l[(size_t)B_*M_*CI_];
__device__ __align__(1024) __nv_bfloat16 s_g_h[(size_t)B_*CI_*M_],  s_g_l[(size_t)B_*CI_*M_];
__device__ __align__(1024) float s_scores[(size_t)B_*N_*M_];
__device__ __align__(1024) __nv_bfloat16 s_p_h[(size_t)B_*N_*M_], s_p_l[(size_t)B_*N_*M_];
__device__ __align__(1024) __nv_bfloat16 s_tT_h[(size_t)B_*N_*CI_], s_tT_l[(size_t)B_*N_*CI_];
__device__ __align__(1024) float s_yT[(size_t)B_*N_*C_];
__device__ double s_bnsum[2*C_];
__device__ float s_bnstat[2*C_];

// ======================= helpers =======================
__device__ __forceinline__ uint32_t smem_u32(const void* p){
    uint32_t a;
    asm("{ .reg .u64 t; cvta.to.shared.u64 t, %1; cvt.u32.u64 %0, t; }" : "=r"(a) : "l"(p));
    return a;
}
__device__ __forceinline__ void cpasync16(uint32_t dst, const void* src){
    asm volatile("cp.async.cg.shared.global [%0], [%1], 16;" :: "r"(dst), "l"(src));
}
__device__ __forceinline__ void ldsm4(uint32_t* r, uint32_t addr){
    asm volatile("ldmatrix.sync.aligned.m8n8.x4.shared.b16 {%0,%1,%2,%3}, [%4];"
        : "=r"(r[0]), "=r"(r[1]), "=r"(r[2]), "=r"(r[3]) : "r"(addr));
}
__device__ __forceinline__ void mma16816(float* c, const uint32_t* a, const uint32_t* b){
    asm volatile("mma.sync.aligned.m16n8k16.row.col.f32.bf16.bf16.f32 "
        "{%0,%1,%2,%3},{%4,%5,%6,%7},{%8,%9},{%0,%1,%2,%3};"
        : "+f"(c[0]), "+f"(c[1]), "+f"(c[2]), "+f"(c[3])
        : "r"(a[0]), "r"(a[1]), "r"(a[2]), "r"(a[3]), "r"(b[0]), "r"(b[1]));
}
__device__ __forceinline__ uint32_t pack_bf16(float x, float y){
    __nv_bfloat162 t;
    t.x = __float2bfloat16(x);
    t.y = __float2bfloat16(y);
    return *reinterpret_cast<uint32_t*>(&t);
}

// ======================= mma.sync GEMM =======================
// D[m][n] = sum_k A[m][k]*B[n][k] (+bias). A,B bf16 hi/lo K-major. fp32 acc.
// CTA tile 128x128, K-chunk 32, 8 warps (warp tile 32m x 64n), cp.async 2-stage.
#define PITCH 80
#define REG_A  10240   // 128 rows * 80B
#define STAGE  40960   // AH|AL|BH|BL
#define GEMM_SMEM (2*STAGE)

__device__ __forceinline__ void load_stage(uint32_t sb, int stage,
    const __nv_bfloat16* __restrict__ Ah, const __nv_bfloat16* __restrict__ Al,
    const __nv_bfloat16* __restrict__ Bh, const __nv_bfloat16* __restrict__ Bl,
    int lda, int ldb, int m0, int n0, int k0, int tid)
{
    uint32_t st = sb + stage * STAGE;
    #pragma unroll
    for (int it = 0; it < 8; it++) {
        int g = tid + it * 256;
        int sel = g >> 9;            // 0 AH, 1 AL, 2 BH, 3 BL
        int r = (g & 511) >> 2;
        int q = g & 3;
        long long off;
        const __nv_bfloat16* src;
        if (sel < 2) {
            off = (long long)(m0 + r) * lda + k0 + q * 8;
            src = (sel == 0 ? Ah : Al) + off;
        } else {
            off = (long long)(n0 + r) * ldb + k0 + q * 8;
            src = (sel == 2 ? Bh : Bl) + off;
        }
        uint32_t dst = st + (uint32_t)sel * REG_A + (uint32_t)(r * PITCH + q * 16);
        cpasync16(dst, src);
    }
}

__device__ __forceinline__ void compute_chunk(uint32_t sb, int stage,
                                              int wm, int wn, int lane,
                                              float acc[2][8][4])
{
    uint32_t st = sb + stage * STAGE;
    uint32_t aBaseH = st + (uint32_t)(wm * 32) * PITCH;
    uint32_t aBaseL = aBaseH + REG_A;
    uint32_t bBaseH = st + 2 * REG_A + (uint32_t)(wn * 64) * PITCH;
    uint32_t bBaseL = bBaseH + REG_A;
    int l15 = lane & 15;
    int lh = lane >> 4;
    int bn_off = ((lane >> 4) & 1) * 8 + (lane & 7);
    int bhalf = (lane >> 3) & 1;

    #pragma unroll
    for (int s = 0; s < 2; s++) {
        uint32_t aoff = (uint32_t)(s * 32 + lh * 16);
        uint32_t aH[2][4], aL[2][4];
        ldsm4(aH[0], aBaseH + (uint32_t)(l15) * PITCH + aoff);
        ldsm4(aH[1], aBaseH + (uint32_t)(16 + l15) * PITCH + aoff);
        ldsm4(aL[0], aBaseL + (uint32_t)(l15) * PITCH + aoff);
        ldsm4(aL[1], aBaseL + (uint32_t)(16 + l15) * PITCH + aoff);

        uint32_t bH[8][2], bL[8][2];
        #pragma unroll
        for (int p = 0; p < 4; p++) {
            uint32_t addr = (uint32_t)((p * 16 + bn_off) * PITCH + s * 32 + bhalf * 16);
            uint32_t r4[4];
            ldsm4(r4, bBaseH + addr);
            bH[2*p][0] = r4[0]; bH[2*p][1] = r4[1];
            bH[2*p+1][0] = r4[2]; bH[2*p+1][1] = r4[3];
            ldsm4(r4, bBaseL + addr);
            bL[2*p][0] = r4[0]; bL[2*p][1] = r4[1];
            bL[2*p+1][0] = r4[2]; bL[2*p+1][1] = r4[3];
        }
        #pragma unroll
        for (int mt = 0; mt < 2; mt++)
            #pragma unroll
            for (int nt = 0; nt < 8; nt++) {
                mma16816(acc[mt][nt], aH[mt], bH[nt]);
                mma16816(acc[mt][nt], aH[mt], bL[nt]);
                mma16816(acc[mt][nt], aL[mt], bH[nt]);
            }
    }
}

// OUTMODE 0: fp32 to Cf ; OUTMODE 1: split bf16 to Ch/Cl
template<int OUTMODE>
__global__ void __launch_bounds__(256, 1)
mm_gemm(const __nv_bfloat16* __restrict__ Ah, const __nv_bfloat16* __restrict__ Al,
        long long a_bs, int lda,
        const __nv_bfloat16* __restrict__ Bh, const __nv_bfloat16* __restrict__ Bl,
        long long b_bs, int ldb,
        float* __restrict__ Cf, __nv_bfloat16* __restrict__ Ch, __nv_bfloat16* __restrict__ Cl,
        long long c_bs, int ldc,
        int K, const float* __restrict__ bias, int bias_mode)
{
    extern __shared__ char sm[];
    uint32_t sb = smem_u32(sm);
    int tid = threadIdx.x;
    int wid = tid >> 5, lane = tid & 31;
    int wm = wid & 3, wn = wid >> 2;
    int z = blockIdx.z;
    int m0 = blockIdx.y * 128;
    int n0 = blockIdx.x * 128;

    const __nv_bfloat16* pAh = Ah + (long long)z * a_bs;
    const __nv_bfloat16* pAl = Al + (long long)z * a_bs;
    const __nv_bfloat16* pBh = Bh + (long long)z * b_bs;
    const __nv_bfloat16* pBl = Bl + (long long)z * b_bs;

    float acc[2][8][4] = {};
    int nc = K / 32;

    load_stage(sb, 0, pAh, pAl, pBh, pBl, lda, ldb, m0, n0, 0, tid);
    asm volatile("cp.async.commit_group;" ::: "memory");

    for (int i = 0; i < nc; i++) {
        if (i + 1 < nc) {
            load_stage(sb, (i + 1) & 1, pAh, pAl, pBh, pBl, lda, ldb, m0, n0, (i + 1) * 32, tid);
            asm volatile("cp.async.commit_group;" ::: "memory");
            asm volatile("cp.async.wait_group 1;" ::: "memory");
        } else {
            asm volatile("cp.async.wait_group 0;" ::: "memory");
        }
        __syncthreads();
        compute_chunk(sb, i & 1, wm, wn, lane, acc);
        __syncthreads();
    }

    // epilogue
    int r = lane >> 2, cg = lane & 3;
    int mb = m0 + wm * 32, nb = n0 + wn * 64;
    #pragma unroll
    for (int mt = 0; mt < 2; mt++) {
        int mrow = mb + mt * 16 + r;
        float br0 = 0.0f, br1 = 0.0f;
        if (bias_mode == 1) { br0 = __ldg(&bias[mrow]); br1 = __ldg(&bias[mrow + 8]); }
        #pragma unroll
        for (int nt = 0; nt < 8; nt++) {
            int col = nb + nt * 8 + cg * 2;
            float bc0 = 0.0f, bc1 = 0.0f;
            if (bias_mode == 2) { bc0 = __ldg(&bias[col]); bc1 = __ldg(&bias[col + 1]); }
            float v00 = acc[mt][nt][0] + br0 + bc0;
            float v01 = acc[mt][nt][1] + br0 + bc1;
            float v10 = acc[mt][nt][2] + br1 + bc0;
            float v11 = acc[mt][nt][3] + br1 + bc1;
            long long o0 = (long long)z * c_bs + (long long)mrow * ldc + col;
            long long o1 = o0 + (long long)8 * ldc;
            if (OUTMODE == 0) {
                *reinterpret_cast<float2*>(Cf + o0) = make_float2(v00, v01);
                *reinterpret_cast<float2*>(Cf + o1) = make_float2(v10, v11);
            } else {
                __nv_bfloat16 h00 = __float2bfloat16(v00), h01 = __float2bfloat16(v01);
                __nv_bfloat16 h10 = __float2bfloat16(v10), h11 = __float2bfloat16(v11);
                *reinterpret_cast<uint32_t*>(Ch + o0) = pack_bf16(v00, v01);
                *reinterpret_cast<uint32_t*>(Ch + o1) = pack_bf16(v10, v11);
                *reinterpret_cast<uint32_t*>(Cl + o0) =
                    pack_bf16(v00 - __bfloat162float(h00), v01 - __bfloat162float(h01));
                *reinterpret_cast<uint32_t*>(Cl + o1) =
                    pack_bf16(v10 - __bfloat162float(h10), v11 - __bfloat162float(h11));
            }
        }
    }
}

// ======================= conversions =======================
__global__ void split_kernel(const float* __restrict__ src, __nv_bfloat16* __restrict__ h,
                             __nv_bfloat16* __restrict__ l, int n) {
    int i = blockIdx.x * blockDim.x + threadIdx.x;
    if (i < n) {
        float v = src[i];
        __nv_bfloat16 hh = __float2bfloat16(v);
        h[i] = hh;
        l[i] = __float2bfloat16(v - __bfloat162float(hh));
    }
}

// src [z][R][CC] -> dst [z][CC][R] split bf16
__global__ void transpose_split_kernel(const float* __restrict__ src,
                                       __nv_bfloat16* __restrict__ dh, __nv_bfloat16* __restrict__ dl,
                                       int R, int CC) {
    __shared__ float tile[32][33];
    int z = blockIdx.z;
    int c0 = blockIdx.x * 32;
    int r0 = blockIdx.y * 32;
    int tx = threadIdx.x, ty = threadIdx.y;
    const float* s = src + (long long)z * R * CC;
    #pragma unroll
    for (int i = 0; i < 4; i++)
        tile[ty + i * 8][tx] = s[(long long)(r0 + ty + i * 8) * CC + c0 + tx];
    __syncthreads();
    __nv_bfloat16* oh = dh + (long long)z * R * CC;
    __nv_bfloat16* ol = dl + (long long)z * R * CC;
    #pragma unroll
    for (int i = 0; i < 4; i++) {
        float v = tile[tx][ty + i * 8];
        __nv_bfloat16 hh = __float2bfloat16(v);
        long long o = (long long)(c0 + ty + i * 8) * R + r0 + tx;
        oh[o] = hh;
        ol[o] = __float2bfloat16(v - __bfloat162float(hh));
    }
}

// x [z][C][64x64] -> pooled transposed split [z][m=1024][c=1024]
__global__ void pool_transpose_split_kernel(const float* __restrict__ x,
                                            __nv_bfloat16* __restrict__ dh, __nv_bfloat16* __restrict__ dl) {
    __shared__ float tile[32][33];
    int z = blockIdx.z;
    int m0 = blockIdx.x * 32;
    int c0 = blockIdx.y * 32;
    int tx = threadIdx.x, ty = threadIdx.y;
    #pragma unroll
    for (int i = 0; i < 4; i++) {
        int c = c0 + ty + i * 8;
        int m = m0 + tx;
        int pi = m >> 5, pj = m & 31;
        const float* b = x + ((long long)z * C_ + c) * 4096 + (pi * 2) * 64 + pj * 2;
        float v = fmaxf(fmaxf(b[0], b[1]), fmaxf(b[64], b[65]));
        tile[ty + i * 8][tx] = v;
    }
    __syncthreads();
    #pragma unroll
    for (int i = 0; i < 4; i++) {
        float v = tile[tx][ty + i * 8];
        __nv_bfloat16 hh = __float2bfloat16(v);
        long long o = ((long long)z * M_ + m0 + ty + i * 8) * C_ + c0 + tx;
        dh[o] = hh;
        dl[o] = __float2bfloat16(v - __bfloat162float(hh));
    }
}

// ======================= softmax (scaled) + split =======================
__global__ void softmax_split_kernel(const float* __restrict__ s,
                                     __nv_bfloat16* __restrict__ ph, __nv_bfloat16* __restrict__ pl,
                                     float scale) {
    const float* row = s + (size_t)blockIdx.x * M_;
    int tid = threadIdx.x;
    float v[4];
    float mx = -1e30f;
    #pragma unroll
    for (int i = 0; i < 4; i++) { v[i] = row[tid + 256 * i] * scale; mx = fmaxf(mx, v[i]); }
    __shared__ float red[8], red2[8];
    #pragma unroll
    for (int o = 16; o > 0; o >>= 1) mx = fmaxf(mx, __shfl_xor_sync(0xffffffffu, mx, o));
    if ((tid & 31) == 0) red[tid >> 5] = mx;
    __syncthreads();
    mx = fmaxf(fmaxf(fmaxf(red[0], red[1]), fmaxf(red[2], red[3])),
               fmaxf(fmaxf(red[4], red[5]), fmaxf(red[6], red[7])));
    float sum = 0.0f;
    #pragma unroll
    for (int i = 0; i < 4; i++) { v[i] = __expf(v[i] - mx); sum += v[i]; }
    #pragma unroll
    for (int o = 16; o > 0; o >>= 1) sum += __shfl_xor_sync(0xffffffffu, sum, o);
    if ((tid & 31) == 0) red2[tid >> 5] = sum;
    __syncthreads();
    sum = (red2[0] + red2[1]) + (red2[2] + red2[3]) + (red2[4] + red2[5]) + (red2[6] + red2[7]);
    float inv = 1.0f / sum;
    size_t base = (size_t)blockIdx.x * M_;
    #pragma unroll
    for (int i = 0; i < 4; i++) {
        float p = v[i] * inv;
        __nv_bfloat16 hh = __float2bfloat16(p);
        ph[base + tid + 256 * i] = hh;
        pl[base + tid + 256 * i] = __float2bfloat16(p - __bfloat162float(hh));
    }
}

// ======================= BatchNorm =======================
__global__ void bn_zero_kernel(double* sums) {
    int i = blockIdx.x * blockDim.x + threadIdx.x;
    if (i < 2 * C_) sums[i] = 0.0;
}
__global__ void bn_stats_kernel(const float* __restrict__ yT, double* __restrict__ sums) {
    int tid = threadIdx.x;
    int c = blockIdx.x * 128 + (tid & 127);
    int half = tid >> 7;
    int r0 = blockIdx.y * 1024 + half * 512;
    float s = 0.0f, s2 = 0.0f;
    for (int r = 0; r < 512; r++) {
        float v = yT[(long long)(r0 + r) * C_ + c];
        s += v; s2 += v * v;
    }
    atomicAdd(&sums[c], (double)s);
    atomicAdd(&sums[C_ + c], (double)s2);
}
__global__ void bn_final_kernel(const double* __restrict__ sums, float* __restrict__ stat) {
    int c = blockIdx.x * blockDim.x + threadIdx.x;
    if (c < C_) {
        double cnt = (double)B_ * N_;
        double mean = sums[c] / cnt;
        double var = sums[C_ + c] / cnt - mean * mean;
        stat[c] = (float)mean;
        stat[C_ + c] = rsqrtf((float)var + 1e-5f);
    }
}
__global__ void bn_apply_kernel(const float* __restrict__ yT, const float* __restrict__ x,
                                const float* __restrict__ stat,
                                const float* __restrict__ gamma, const float* __restrict__ beta,
                                float* __restrict__ out) {
    __shared__ float tile[32][33];
    int z = blockIdx.z;
    int n0 = blockIdx.x * 32;
    int c0 = blockIdx.y * 32;
    int tx = threadIdx.x, ty = threadIdx.y;
    #pragma unroll
    for (int i = 0; i < 4; i++)
        tile[ty + i * 8][tx] = yT[((long long)z * N_ + n0 + ty + i * 8) * C_ + c0 + tx];
    __syncthreads();
    #pragma unroll
    for (int i = 0; i < 4; i++) {
        int c = c0 + ty + i * 8;
        int n = n0 + tx;
        float mean = stat[c], rstd = stat[C_ + c];
        long long o = ((long long)z * C_ + c) * N_ + n;
        out[o] = (tile[tx][ty + i * 8] - mean) * rstd * gamma[c] + beta[c] + x[o];
    }
}

// ======================= launch =======================
extern "C" void kernel_launch(void* const* d_in, const int* in_sizes, int n_in,
                              void* d_out, int out_size) {
    const float* x       = (const float*)d_in[0];
    const float* w_theta = (const float*)d_in[1];
    const float* b_theta = (const float*)d_in[2];
    const float* w_phi   = (const float*)d_in[3];
    const float* b_phi   = (const float*)d_in[4];
    const float* w_g     = (const float*)d_in[5];
    const float* b_g     = (const float*)d_in[6];
    const float* w_out   = (const float*)d_in[7];
    const float* b_out   = (const float*)d_in[8];
    const float* gamma   = (const float*)d_in[9];
    const float* beta    = (const float*)d_in[10];
    float* out = (float*)d_out;

    cudaFuncSetAttribute(mm_gemm<0>, cudaFuncAttributeMaxDynamicSharedMemorySize, GEMM_SMEM);
    cudaFuncSetAttribute(mm_gemm<1>, cudaFuncAttributeMaxDynamicSharedMemorySize, GEMM_SMEM);

    __nv_bfloat16 *xT_h, *xT_l, *pxT_h, *pxT_l;
    __nv_bfloat16 *wth_h, *wth_l, *wph_h, *wph_l, *wg_h, *wg_l, *wo_h, *wo_l;
    __nv_bfloat16 *thT_h, *thT_l, *phT_h, *phT_l, *g_h, *g_l, *p_h, *p_l, *tT_h, *tT_l;
    float *scores, *yT, *bnstat;
    double *bnsum;
    cudaGetSymbolAddress((void**)&xT_h, s_xT_h);   cudaGetSymbolAddress((void**)&xT_l, s_xT_l);
    cudaGetSymbolAddress((void**)&pxT_h, s_pxT_h); cudaGetSymbolAddress((void**)&pxT_l, s_pxT_l);
    cudaGetSymbolAddress((void**)&wth_h, s_wth_h); cudaGetSymbolAddress((void**)&wth_l, s_wth_l);
    cudaGetSymbolAddress((void**)&wph_h, s_wph_h); cudaGetSymbolAddress((void**)&wph_l, s_wph_l);
    cudaGetSymbolAddress((void**)&wg_h, s_wg_h);   cudaGetSymbolAddress((void**)&wg_l, s_wg_l);
    cudaGetSymbolAddress((void**)&wo_h, s_wo_h);   cudaGetSymbolAddress((void**)&wo_l, s_wo_l);
    cudaGetSymbolAddress((void**)&thT_h, s_thT_h); cudaGetSymbolAddress((void**)&thT_l, s_thT_l);
    cudaGetSymbolAddress((void**)&phT_h, s_phT_h); cudaGetSymbolAddress((void**)&phT_l, s_phT_l);
    cudaGetSymbolAddress((void**)&g_h, s_g_h);     cudaGetSymbolAddress((void**)&g_l, s_g_l);
    cudaGetSymbolAddress((void**)&p_h, s_p_h);     cudaGetSymbolAddress((void**)&p_l, s_p_l);
    cudaGetSymbolAddress((void**)&tT_h, s_tT_h);   cudaGetSymbolAddress((void**)&tT_l, s_tT_l);
    cudaGetSymbolAddress((void**)&scores, s_scores);
    cudaGetSymbolAddress((void**)&yT, s_yT);
    cudaGetSymbolAddress((void**)&bnsum, s_bnsum);
    cudaGetSymbolAddress((void**)&bnstat, s_bnstat);

    dim3 tb(32, 8);

    split_kernel<<<(CI_ * C_ + 255) / 256, 256>>>(w_theta, wth_h, wth_l, CI_ * C_);
    split_kernel<<<(CI_ * C_ + 255) / 256, 256>>>(w_phi, wph_h, wph_l, CI_ * C_);
    split_kernel<<<(CI_ * C_ + 255) / 256, 256>>>(w_g, wg_h, wg_l, CI_ * C_);
    split_kernel<<<(C_ * CI_ + 255) / 256, 256>>>(w_out, wo_h, wo_l, C_ * CI_);

    transpose_split_kernel<<<dim3(N_ / 32, C_ / 32, B_), tb>>>(x, xT_h, xT_l, C_, N_);
    pool_transpose_split_kernel<<<dim3(M_ / 32, C_ / 32, B_), tb>>>(x, pxT_h, pxT_l);

    // GEMM1: thT[n][ci] = xT @ w_theta^T ; rows=4096, cols=512, K=1024
    mm_gemm<1><<<dim3(CI_ / 128, N_ / 128, B_), 256, GEMM_SMEM>>>(
        xT_h, xT_l, (long long)N_ * C_, C_,
        wth_h, wth_l, 0, C_,
        nullptr, thT_h, thT_l, (long long)N_ * CI_, CI_,
        C_, b_theta, 2);
    // GEMM2: phT[m][ci] ; rows=1024, cols=512, K=1024
    mm_gemm<1><<<dim3(CI_ / 128, M_ / 128, B_), 256, GEMM_SMEM>>>(
        pxT_h, pxT_l, (long long)M_ * C_, C_,
        wph_h, wph_l, 0, C_,
        nullptr, phT_h, phT_l, (long long)M_ * CI_, CI_,
        C_, b_phi, 2);
    // GEMM3: g[ci][m] ; rows=512, cols=1024, K=1024
    mm_gemm<1><<<dim3(M_ / 128, CI_ / 128, B_), 256, GEMM_SMEM>>>(
        wg_h, wg_l, 0, C_,
        pxT_h, pxT_l, (long long)M_ * C_, C_,
        nullptr, g_h, g_l, (long long)CI_ * M_, M_,
        C_, b_g, 1);
    // GEMM4: scores[n][m] ; rows=4096, cols=1024, K=512
    mm_gemm<0><<<dim3(M_ / 128, N_ / 128, B_), 256, GEMM_SMEM>>>(
        thT_h, thT_l, (long long)N_ * CI_, CI_,
        phT_h, phT_l, (long long)M_ * CI_, CI_,
        scores, nullptr, nullptr, (long long)N_ * M_, M_,
        CI_, nullptr, 0);
    softmax_split_kernel<<<B_ * N_, 256>>>(scores, p_h, p_l, rsqrtf((float)CI_));
    // GEMM5: tT[n][ci] = p @ g^T ; rows=4096, cols=512, K=1024
    mm_gemm<1><<<dim3(CI_ / 128, N_ / 128, B_), 256, GEMM_SMEM>>>(
        p_h, p_l, (long long)N_ * M_, M_,
        g_h, g_l, (long long)CI_ * M_, M_,
        nullptr, tT_h, tT_l, (long long)N_ * CI_, CI_,
        M_, nullptr, 0);
    // GEMM6: yT[n][c] = tT @ w_out^T ; rows=4096, cols=1024, K=512
    mm_gemm<0><<<dim3(C_ / 128, N_ / 128, B_), 256, GEMM_SMEM>>>(
        tT_h, tT_l, (long long)N_ * CI_, CI_,
        wo_h, wo_l, 0, CI_,
        yT, nullptr, nullptr, (long long)N_ * C_, C_,
        CI_, b_out, 2);

    bn_zero_kernel<<<8, 256>>>(bnsum);
    bn_stats_kernel<<<dim3(C_ / 128, 32), 256>>>(yT, bnsum);
    bn_final_kernel<<<4, 256>>>(bnsum, bnstat);
    bn_apply_kernel<<<dim3(N_ / 32, C_ / 32, B_), tb>>>(yT, x, bnstat, gamma, beta, out);
}

// round 4
// speedup vs baseline: 5.1526x; 1.0211x over previous
#include <cuda_runtime.h>
#include <cuda_bf16.h>
#include <cstdint>
#include <math.h>

#define B_  8
#define C_  1024
#define CI_ 512
#define N_  4096
#define M_  1024

// ======================= scratch (device globals) =======================
__device__ __align__(1024) __nv_bfloat16 s_xT_h[(size_t)B_*N_*C_];   // [b][n][c]
__device__ __align__(1024) __nv_bfloat16 s_xT_l[(size_t)B_*N_*C_];
__device__ __align__(1024) __nv_bfloat16 s_pxT_h[(size_t)B_*M_*C_];  // [b][m][c]
__device__ __align__(1024) __nv_bfloat16 s_pxT_l[(size_t)B_*M_*C_];
__device__ __align__(1024) __nv_bfloat16 s_wth_h[CI_*C_], s_wth_l[CI_*C_];
__device__ __align__(1024) __nv_bfloat16 s_wph_h[CI_*C_], s_wph_l[CI_*C_];
__device__ __align__(1024) __nv_bfloat16 s_wg_h[CI_*C_],  s_wg_l[CI_*C_];
__device__ __align__(1024) __nv_bfloat16 s_wo_h[C_*CI_],  s_wo_l[C_*CI_];
__device__ __align__(1024) __nv_bfloat16 s_thT_h[(size_t)B_*N_*CI_], s_thT_l[(size_t)B_*N_*CI_];
__device__ __align__(1024) __nv_bfloat16 s_phT_h[(size_t)B_*M_*CI_], s_phT_l[(size_t)B_*M_*CI_];
__device__ __align__(1024) __nv_bfloat16 s_g_h[(size_t)B_*CI_*M_],  s_g_l[(size_t)B_*CI_*M_];
__device__ __align__(1024) float s_scores[(size_t)B_*N_*M_];
__device__ __align__(1024) __nv_bfloat16 s_p_h[(size_t)B_*N_*M_], s_p_l[(size_t)B_*N_*M_];
__device__ __align__(1024) __nv_bfloat16 s_tT_h[(size_t)B_*N_*CI_], s_tT_l[(size_t)B_*N_*CI_];
__device__ __align__(1024) float s_yT[(size_t)B_*N_*C_];
__device__ double s_bnsum[2*C_];
__device__ float s_bnstat[2*C_];

// ======================= helpers =======================
__device__ __forceinline__ uint32_t smem_u32(const void* p){
    uint32_t a;
    asm("{ .reg .u64 t; cvta.to.shared.u64 t, %1; cvt.u32.u64 %0, t; }" : "=r"(a) : "l"(p));
    return a;
}
__device__ __forceinline__ void cpasync16(uint32_t dst, const void* src){
    asm volatile("cp.async.cg.shared.global [%0], [%1], 16;" :: "r"(dst), "l"(src));
}
__device__ __forceinline__ void ldsm4(uint32_t* r, uint32_t addr){
    asm volatile("ldmatrix.sync.aligned.m8n8.x4.shared.b16 {%0,%1,%2,%3}, [%4];"
        : "=r"(r[0]), "=r"(r[1]), "=r"(r[2]), "=r"(r[3]) : "r"(addr));
}
__device__ __forceinline__ void mma16816(float* c, const uint32_t* a, const uint32_t* b){
    asm volatile("mma.sync.aligned.m16n8k16.row.col.f32.bf16.bf16.f32 "
        "{%0,%1,%2,%3},{%4,%5,%6,%7},{%8,%9},{%0,%1,%2,%3};"
        : "+f"(c[0]), "+f"(c[1]), "+f"(c[2]), "+f"(c[3])
        : "r"(a[0]), "r"(a[1]), "r"(a[2]), "r"(a[3]), "r"(b[0]), "r"(b[1]));
}
__device__ __forceinline__ uint32_t pack_bf16(float x, float y){
    __nv_bfloat162 t;
    t.x = __float2bfloat16(x);
    t.y = __float2bfloat16(y);
    return *reinterpret_cast<uint32_t*>(&t);
}

// ======================= mma.sync GEMM =======================
// D[m][n] = sum_k A[m][k]*B[n][k] (+bias). A,B bf16 hi/lo K-major. fp32 acc.
// CTA tile 128x128, K-chunk 32, 8 warps (warp tile 32m x 64n), 4-stage cp.async.
#define PITCH 80
#define REG_A  10240   // 128 rows * 80B
#define STAGE  40960   // AH|AL|BH|BL
#define NSTAGE 4
#define GEMM_SMEM (NSTAGE*STAGE)

__device__ __forceinline__ void load_stage(uint32_t sb, int stage,
    const __nv_bfloat16* __restrict__ Ah, const __nv_bfloat16* __restrict__ Al,
    const __nv_bfloat16* __restrict__ Bh, const __nv_bfloat16* __restrict__ Bl,
    int lda, int ldb, int m0, int n0, int k0, int tid)
{
    uint32_t st = sb + stage * STAGE;
    #pragma unroll
    for (int it = 0; it < 8; it++) {
        int g = tid + it * 256;
        int sel = g >> 9;            // 0 AH, 1 AL, 2 BH, 3 BL
        int r = (g & 511) >> 2;
        int q = g & 3;
        long long off;
        const __nv_bfloat16* src;
        if (sel < 2) {
            off = (long long)(m0 + r) * lda + k0 + q * 8;
            src = (sel == 0 ? Ah : Al) + off;
        } else {
            off = (long long)(n0 + r) * ldb + k0 + q * 8;
            src = (sel == 2 ? Bh : Bl) + off;
        }
        uint32_t dst = st + (uint32_t)sel * REG_A + (uint32_t)(r * PITCH + q * 16);
        cpasync16(dst, src);
    }
}

__device__ __forceinline__ void compute_chunk(uint32_t sb, int stage,
                                              int wm, int wn, int lane,
                                              float acc[2][8][4])
{
    uint32_t st = sb + stage * STAGE;
    uint32_t aBaseH = st + (uint32_t)(wm * 32) * PITCH;
    uint32_t aBaseL = aBaseH + REG_A;
    uint32_t bBaseH = st + 2 * REG_A + (uint32_t)(wn * 64) * PITCH;
    uint32_t bBaseL = bBaseH + REG_A;
    int l15 = lane & 15;
    int lh = lane >> 4;
    int bn_off = ((lane >> 4) & 1) * 8 + (lane & 7);
    int bhalf = (lane >> 3) & 1;

    #pragma unroll
    for (int s = 0; s < 2; s++) {
        uint32_t aoff = (uint32_t)(s * 32 + lh * 16);
        uint32_t aH[2][4], aL[2][4];
        ldsm4(aH[0], aBaseH + (uint32_t)(l15) * PITCH + aoff);
        ldsm4(aH[1], aBaseH + (uint32_t)(16 + l15) * PITCH + aoff);
        ldsm4(aL[0], aBaseL + (uint32_t)(l15) * PITCH + aoff);
        ldsm4(aL[1], aBaseL + (uint32_t)(16 + l15) * PITCH + aoff);

        uint32_t bH[8][2], bL[8][2];
        #pragma unroll
        for (int p = 0; p < 4; p++) {
            uint32_t addr = (uint32_t)((p * 16 + bn_off) * PITCH + s * 32 + bhalf * 16);
            uint32_t r4[4];
            ldsm4(r4, bBaseH + addr);
            bH[2*p][0] = r4[0]; bH[2*p][1] = r4[1];
            bH[2*p+1][0] = r4[2]; bH[2*p+1][1] = r4[3];
            ldsm4(r4, bBaseL + addr);
            bL[2*p][0] = r4[0]; bL[2*p][1] = r4[1];
            bL[2*p+1][0] = r4[2]; bL[2*p+1][1] = r4[3];
        }
        // product passes: all 16 accumulators independent within a pass ->
        // no back-to-back dependent MMAs on the same accumulator.
        #pragma unroll
        for (int mt = 0; mt < 2; mt++)
            #pragma unroll
            for (int nt = 0; nt < 8; nt++)
                mma16816(acc[mt][nt], aH[mt], bH[nt]);
        #pragma unroll
        for (int mt = 0; mt < 2; mt++)
            #pragma unroll
            for (int nt = 0; nt < 8; nt++)
                mma16816(acc[mt][nt], aH[mt], bL[nt]);
        #pragma unroll
        for (int mt = 0; mt < 2; mt++)
            #pragma unroll
            for (int nt = 0; nt < 8; nt++)
                mma16816(acc[mt][nt], aL[mt], bH[nt]);
    }
}

// OUTMODE 0: fp32 to Cf ; OUTMODE 1: split bf16 to Ch/Cl
template<int OUTMODE>
__global__ void __launch_bounds__(256, 1)
mm_gemm(const __nv_bfloat16* __restrict__ Ah, const __nv_bfloat16* __restrict__ Al,
        long long a_bs, int lda,
        const __nv_bfloat16* __restrict__ Bh, const __nv_bfloat16* __restrict__ Bl,
        long long b_bs, int ldb,
        float* __restrict__ Cf, __nv_bfloat16* __restrict__ Ch, __nv_bfloat16* __restrict__ Cl,
        long long c_bs, int ldc,
        int K, const float* __restrict__ bias, int bias_mode)
{
    extern __shared__ char sm[];
    uint32_t sb = smem_u32(sm);
    int tid = threadIdx.x;
    int wid = tid >> 5, lane = tid & 31;
    int wm = wid & 3, wn = wid >> 2;
    int z = blockIdx.z;
    int m0 = blockIdx.y * 128;
    int n0 = blockIdx.x * 128;

    const __nv_bfloat16* pAh = Ah + (long long)z * a_bs;
    const __nv_bfloat16* pAl = Al + (long long)z * a_bs;
    const __nv_bfloat16* pBh = Bh + (long long)z * b_bs;
    const __nv_bfloat16* pBl = Bl + (long long)z * b_bs;

    float acc[2][8][4] = {};
    int nc = K / 32;

    // prologue: fill 3 stages
    #pragma unroll
    for (int s = 0; s < 3; s++) {
        if (s < nc) {
            load_stage(sb, s, pAh, pAl, pBh, pBl, lda, ldb, m0, n0, s * 32, tid);
        }
        asm volatile("cp.async.commit_group;" ::: "memory");
    }

    for (int i = 0; i < nc; i++) {
        asm volatile("cp.async.wait_group 2;" ::: "memory");  // stage i ready
        __syncthreads();                                      // everyone done with stage i-1's buffer reuse target
        if (i + 3 < nc)
            load_stage(sb, (i + 3) & (NSTAGE - 1), pAh, pAl, pBh, pBl, lda, ldb, m0, n0, (i + 3) * 32, tid);
        asm volatile("cp.async.commit_group;" ::: "memory");
        compute_chunk(sb, i & (NSTAGE - 1), wm, wn, lane, acc);
    }

    // epilogue
    int r = lane >> 2, cg = lane & 3;
    int mb = m0 + wm * 32, nb = n0 + wn * 64;
    #pragma unroll
    for (int mt = 0; mt < 2; mt++) {
        int mrow = mb + mt * 16 + r;
        float br0 = 0.0f, br1 = 0.0f;
        if (bias_mode == 1) { br0 = __ldg(&bias[mrow]); br1 = __ldg(&bias[mrow + 8]); }
        #pragma unroll
        for (int nt = 0; nt < 8; nt++) {
            int col = nb + nt * 8 + cg * 2;
            float bc0 = 0.0f, bc1 = 0.0f;
            if (bias_mode == 2) { bc0 = __ldg(&bias[col]); bc1 = __ldg(&bias[col + 1]); }
            float v00 = acc[mt][nt][0] + br0 + bc0;
            float v01 = acc[mt][nt][1] + br0 + bc1;
            float v10 = acc[mt][nt][2] + br1 + bc0;
            float v11 = acc[mt][nt][3] + br1 + bc1;
            long long o0 = (long long)z * c_bs + (long long)mrow * ldc + col;
            long long o1 = o0 + (long long)8 * ldc;
            if (OUTMODE == 0) {
                *reinterpret_cast<float2*>(Cf + o0) = make_float2(v00, v01);
                *reinterpret_cast<float2*>(Cf + o1) = make_float2(v10, v11);
            } else {
                __nv_bfloat16 h00 = __float2bfloat16(v00), h01 = __float2bfloat16(v01);
                __nv_bfloat16 h10 = __float2bfloat16(v10), h11 = __float2bfloat16(v11);
                *reinterpret_cast<uint32_t*>(Ch + o0) = pack_bf16(v00, v01);
                *reinterpret_cast<uint32_t*>(Ch + o1) = pack_bf16(v10, v11);
                *reinterpret_cast<uint32_t*>(Cl + o0) =
                    pack_bf16(v00 - __bfloat162float(h00), v01 - __bfloat162float(h01));
                *reinterpret_cast<uint32_t*>(Cl + o1) =
                    pack_bf16(v10 - __bfloat162float(h10), v11 - __bfloat162float(h11));
            }
        }
    }
}

// ======================= conversions =======================
__global__ void split_kernel(const float* __restrict__ src, __nv_bfloat16* __restrict__ h,
                             __nv_bfloat16* __restrict__ l, int n) {
    int i = blockIdx.x * blockDim.x + threadIdx.x;
    if (i < n) {
        float v = src[i];
        __nv_bfloat16 hh = __float2bfloat16(v);
        h[i] = hh;
        l[i] = __float2bfloat16(v - __bfloat162float(hh));
    }
}

// src [z][R][CC] -> dst [z][CC][R] split bf16
__global__ void transpose_split_kernel(const float* __restrict__ src,
                                       __nv_bfloat16* __restrict__ dh, __nv_bfloat16* __restrict__ dl,
                                       int R, int CC) {
    __shared__ float tile[32][33];
    int z = blockIdx.z;
    int c0 = blockIdx.x * 32;
    int r0 = blockIdx.y * 32;
    int tx = threadIdx.x, ty = threadIdx.y;
    const float* s = src + (long long)z * R * CC;
    #pragma unroll
    for (int i = 0; i < 4; i++)
        tile[ty + i * 8][tx] = s[(long long)(r0 + ty + i * 8) * CC + c0 + tx];
    __syncthreads();
    __nv_bfloat16* oh = dh + (long long)z * R * CC;
    __nv_bfloat16* ol = dl + (long long)z * R * CC;
    #pragma unroll
    for (int i = 0; i < 4; i++) {
        float v = tile[tx][ty + i * 8];
        __nv_bfloat16 hh = __float2bfloat16(v);
        long long o = (long long)(c0 + ty + i * 8) * R + r0 + tx;
        oh[o] = hh;
        ol[o] = __float2bfloat16(v - __bfloat162float(hh));
    }
}

// x [z][C][64x64] -> pooled transposed split [z][m=1024][c=1024]
__global__ void pool_transpose_split_kernel(const float* __restrict__ x,
                                            __nv_bfloat16* __restrict__ dh, __nv_bfloat16* __restrict__ dl) {
    __shared__ float tile[32][33];
    int z = blockIdx.z;
    int m0 = blockIdx.x * 32;
    int c0 = blockIdx.y * 32;
    int tx = threadIdx.x, ty = threadIdx.y;
    #pragma unroll
    for (int i = 0; i < 4; i++) {
        int c = c0 + ty + i * 8;
        int m = m0 + tx;
        int pi = m >> 5, pj = m & 31;
        const float* b = x + ((long long)z * C_ + c) * 4096 + (pi * 2) * 64 + pj * 2;
        float v = fmaxf(fmaxf(b[0], b[1]), fmaxf(b[64], b[65]));
        tile[ty + i * 8][tx] = v;
    }
    __syncthreads();
    #pragma unroll
    for (int i = 0; i < 4; i++) {
        float v = tile[tx][ty + i * 8];
        __nv_bfloat16 hh = __float2bfloat16(v);
        long long o = ((long long)z * M_ + m0 + ty + i * 8) * C_ + c0 + tx;
        dh[o] = hh;
        dl[o] = __float2bfloat16(v - __bfloat162float(hh));
    }
}

// ======================= softmax (scaled) + split =======================
__global__ void softmax_split_kernel(const float* __restrict__ s,
                                     __nv_bfloat16* __restrict__ ph, __nv_bfloat16* __restrict__ pl,
                                     float scale) {
    const float* row = s + (size_t)blockIdx.x * M_;
    int tid = threadIdx.x;
    float v[4];
    float mx = -1e30f;
    #pragma unroll
    for (int i = 0; i < 4; i++) { v[i] = row[tid + 256 * i] * scale; mx = fmaxf(mx, v[i]); }
    __shared__ float red[8], red2[8];
    #pragma unroll
    for (int o = 16; o > 0; o >>= 1) mx = fmaxf(mx, __shfl_xor_sync(0xffffffffu, mx, o));
    if ((tid & 31) == 0) red[tid >> 5] = mx;
    __syncthreads();
    mx = fmaxf(fmaxf(fmaxf(red[0], red[1]), fmaxf(red[2], red[3])),
               fmaxf(fmaxf(red[4], red[5]), fmaxf(red[6], red[7])));
    float sum = 0.0f;
    #pragma unroll
    for (int i = 0; i < 4; i++) { v[i] = __expf(v[i] - mx); sum += v[i]; }
    #pragma unroll
    for (int o = 16; o > 0; o >>= 1) sum += __shfl_xor_sync(0xffffffffu, sum, o);
    if ((tid & 31) == 0) red2[tid >> 5] = sum;
    __syncthreads();
    sum = (red2[0] + red2[1]) + (red2[2] + red2[3]) + (red2[4] + red2[5]) + (red2[6] + red2[7]);
    float inv = 1.0f / sum;
    size_t base = (size_t)blockIdx.x * M_;
    #pragma unroll
    for (int i = 0; i < 4; i++) {
        float p = v[i] * inv;
        __nv_bfloat16 hh = __float2bfloat16(p);
        ph[base + tid + 256 * i] = hh;
        pl[base + tid + 256 * i] = __float2bfloat16(p - __bfloat162float(hh));
    }
}

// ======================= BatchNorm =======================
__global__ void bn_zero_kernel(double* sums) {
    int i = blockIdx.x * blockDim.x + threadIdx.x;
    if (i < 2 * C_) sums[i] = 0.0;
}
__global__ void bn_stats_kernel(const float* __restrict__ yT, double* __restrict__ sums) {
    int tid = threadIdx.x;
    int c = blockIdx.x * 128 + (tid & 127);
    int half = tid >> 7;
    int r0 = blockIdx.y * 1024 + half * 512;
    float s = 0.0f, s2 = 0.0f;
    for (int r = 0; r < 512; r++) {
        float v = yT[(long long)(r0 + r) * C_ + c];
        s += v; s2 += v * v;
    }
    atomicAdd(&sums[c], (double)s);
    atomicAdd(&sums[C_ + c], (double)s2);
}
__global__ void bn_final_kernel(const double* __restrict__ sums, float* __restrict__ stat) {
    int c = blockIdx.x * blockDim.x + threadIdx.x;
    if (c < C_) {
        double cnt = (double)B_ * N_;
        double mean = sums[c] / cnt;
        double var = sums[C_ + c] / cnt - mean * mean;
        stat[c] = (float)mean;
        stat[C_ + c] = rsqrtf((float)var + 1e-5f);
    }
}
__global__ void bn_apply_kernel(const float* __restrict__ yT, const float* __restrict__ x,
                                const float* __restrict__ stat,
                                const float* __restrict__ gamma, const float* __restrict__ beta,
                                float* __restrict__ out) {
    __shared__ float tile[32][33];
    int z = blockIdx.z;
    int n0 = blockIdx.x * 32;
    int c0 = blockIdx.y * 32;
    int tx = threadIdx.x, ty = threadIdx.y;
    #pragma unroll
    for (int i = 0; i < 4; i++)
        tile[ty + i * 8][tx] = yT[((long long)z * N_ + n0 + ty + i * 8) * C_ + c0 + tx];
    __syncthreads();
    #pragma unroll
    for (int i = 0; i < 4; i++) {
        int c = c0 + ty + i * 8;
        int n = n0 + tx;
        float mean = stat[c], rstd = stat[C_ + c];
        long long o = ((long long)z * C_ + c) * N_ + n;
        out[o] = (tile[tx][ty + i * 8] - mean) * rstd * gamma[c] + beta[c] + x[o];
    }
}

// ======================= launch =======================
extern "C" void kernel_launch(void* const* d_in, const int* in_sizes, int n_in,
                              void* d_out, int out_size) {
    const float* x       = (const float*)d_in[0];
    const float* w_theta = (const float*)d_in[1];
    const float* b_theta = (const float*)d_in[2];
    const float* w_phi   = (const float*)d_in[3];
    const float* b_phi   = (const float*)d_in[4];
    const float* w_g     = (const float*)d_in[5];
    const float* b_g     = (const float*)d_in[6];
    const float* w_out   = (const float*)d_in[7];
    const float* b_out   = (const float*)d_in[8];
    const float* gamma   = (const float*)d_in[9];
    const float* beta    = (const float*)d_in[10];
    float* out = (float*)d_out;

    cudaFuncSetAttribute(mm_gemm<0>, cudaFuncAttributeMaxDynamicSharedMemorySize, GEMM_SMEM);
    cudaFuncSetAttribute(mm_gemm<1>, cudaFuncAttributeMaxDynamicSharedMemorySize, GEMM_SMEM);

    __nv_bfloat16 *xT_h, *xT_l, *pxT_h, *pxT_l;
    __nv_bfloat16 *wth_h, *wth_l, *wph_h, *wph_l, *wg_h, *wg_l, *wo_h, *wo_l;
    __nv_bfloat16 *thT_h, *thT_l, *phT_h, *phT_l, *g_h, *g_l, *p_h, *p_l, *tT_h, *tT_l;
    float *scores, *yT, *bnstat;
    double *bnsum;
    cudaGetSymbolAddress((void**)&xT_h, s_xT_h);   cudaGetSymbolAddress((void**)&xT_l, s_xT_l);
    cudaGetSymbolAddress((void**)&pxT_h, s_pxT_h); cudaGetSymbolAddress((void**)&pxT_l, s_pxT_l);
    cudaGetSymbolAddress((void**)&wth_h, s_wth_h); cudaGetSymbolAddress((void**)&wth_l, s_wth_l);
    cudaGetSymbolAddress((void**)&wph_h, s_wph_h); cudaGetSymbolAddress((void**)&wph_l, s_wph_l);
    cudaGetSymbolAddress((void**)&wg_h, s_wg_h);   cudaGetSymbolAddress((void**)&wg_l, s_wg_l);
    cudaGetSymbolAddress((void**)&wo_h, s_wo_h);   cudaGetSymbolAddress((void**)&wo_l, s_wo_l);
    cudaGetSymbolAddress((void**)&thT_h, s_thT_h); cudaGetSymbolAddress((void**)&thT_l, s_thT_l);
    cudaGetSymbolAddress((void**)&phT_h, s_phT_h); cudaGetSymbolAddress((void**)&phT_l, s_phT_l);
    cudaGetSymbolAddress((void**)&g_h, s_g_h);     cudaGetSymbolAddress((void**)&g_l, s_g_l);
    cudaGetSymbolAddress((void**)&p_h, s_p_h);     cudaGetSymbolAddress((void**)&p_l, s_p_l);
    cudaGetSymbolAddress((void**)&tT_h, s_tT_h);   cudaGetSymbolAddress((void**)&tT_l, s_tT_l);
    cudaGetSymbolAddress((void**)&scores, s_scores);
    cudaGetSymbolAddress((void**)&yT, s_yT);
    cudaGetSymbolAddress((void**)&bnsum, s_bnsum);
    cudaGetSymbolAddress((void**)&bnstat, s_bnstat);

    dim3 tb(32, 8);

    split_kernel<<<(CI_ * C_ + 255) / 256, 256>>>(w_theta, wth_h, wth_l, CI_ * C_);
    split_kernel<<<(CI_ * C_ + 255) / 256, 256>>>(w_phi, wph_h, wph_l, CI_ * C_);
    split_kernel<<<(CI_ * C_ + 255) / 256, 256>>>(w_g, wg_h, wg_l, CI_ * C_);
    split_kernel<<<(C_ * CI_ + 255) / 256, 256>>>(w_out, wo_h, wo_l, C_ * CI_);

    transpose_split_kernel<<<dim3(N_ / 32, C_ / 32, B_), tb>>>(x, xT_h, xT_l, C_, N_);
    pool_transpose_split_kernel<<<dim3(M_ / 32, C_ / 32, B_), tb>>>(x, pxT_h, pxT_l);

    // GEMM1: thT[n][ci] = xT @ w_theta^T ; rows=4096, cols=512, K=1024
    mm_gemm<1><<<dim3(CI_ / 128, N_ / 128, B_), 256, GEMM_SMEM>>>(
        xT_h, xT_l, (long long)N_ * C_, C_,
        wth_h, wth_l, 0, C_,
        nullptr, thT_h, thT_l, (long long)N_ * CI_, CI_,
        C_, b_theta, 2);
    // GEMM2: phT[m][ci] ; rows=1024, cols=512, K=1024
    mm_gemm<1><<<dim3(CI_ / 128, M_ / 128, B_), 256, GEMM_SMEM>>>(
        pxT_h, pxT_l, (long long)M_ * C_, C_,
        wph_h, wph_l, 0, C_,
        nullptr, phT_h, phT_l, (long long)M_ * CI_, CI_,
        C_, b_phi, 2);
    // GEMM3: g[ci][m] ; rows=512, cols=1024, K=1024
    mm_gemm<1><<<dim3(M_ / 128, CI_ / 128, B_), 256, GEMM_SMEM>>>(
        wg_h, wg_l, 0, C_,
        pxT_h, pxT_l, (long long)M_ * C_, C_,
        nullptr, g_h, g_l, (long long)CI_ * M_, M_,
        C_, b_g, 1);
    // GEMM4: scores[n][m] ; rows=4096, cols=1024, K=512
    mm_gemm<0><<<dim3(M_ / 128, N_ / 128, B_), 256, GEMM_SMEM>>>(
        thT_h, thT_l, (long long)N_ * CI_, CI_,
        phT_h, phT_l, (long long)M_ * CI_, CI_,
        scores, nullptr, nullptr, (long long)N_ * M_, M_,
        CI_, nullptr, 0);
    softmax_split_kernel<<<B_ * N_, 256>>>(scores, p_h, p_l, rsqrtf((float)CI_));
    // GEMM5: tT[n][ci] = p @ g^T ; rows=4096, cols=512, K=1024
    mm_gemm<1><<<dim3(CI_ / 128, N_ / 128, B_), 256, GEMM_SMEM>>>(
        p_h, p_l, (long long)N_ * M_, M_,
        g_h, g_l, (long long)CI_ * M_, M_,
        nullptr, tT_h, tT_l, (long long)N_ * CI_, CI_,
        M_, nullptr, 0);
    // GEMM6: yT[n][c] = tT @ w_out^T ; rows=4096, cols=1024, K=512
    mm_gemm<0><<<dim3(C_ / 128, N_ / 128, B_), 256, GEMM_SMEM>>>(
        tT_h, tT_l, (long long)N_ * CI_, CI_,
        wo_h, wo_l, 0, CI_,
        yT, nullptr, nullptr, (long long)N_ * C_, C_,
        CI_, b_out, 2);

    bn_zero_kernel<<<8, 256>>>(bnsum);
    bn_stats_kernel<<<dim3(C_ / 128, 32), 256>>>(yT, bnsum);
    bn_final_kernel<<<4, 256>>>(bnsum, bnstat);
    bn_apply_kernel<<<dim3(N_ / 32, C_ / 32, B_), tb>>>(yT, x, bnstat, gamma, beta, out);
}

// round 5
// speedup vs baseline: 5.4494x; 1.0576x over previous
#include <cuda_runtime.h>
#include <cuda_bf16.h>
#include <cstdint>
#include <math.h>

#define B_  8
#define C_  1024
#define CI_ 512
#define N_  4096
#define M_  1024

// ======================= scratch (device globals) =======================
__device__ __align__(1024) __nv_bfloat16 s_xT_h[(size_t)B_*N_*C_];   // [b][n][c]
__device__ __align__(1024) __nv_bfloat16 s_xT_l[(size_t)B_*N_*C_];
__device__ __align__(1024) __nv_bfloat16 s_pxT_h[(size_t)B_*M_*C_];  // [b][m][c]
__device__ __align__(1024) __nv_bfloat16 s_pxT_l[(size_t)B_*M_*C_];
__device__ __align__(1024) __nv_bfloat16 s_wth_h[CI_*C_], s_wth_l[CI_*C_];
__device__ __align__(1024) __nv_bfloat16 s_wph_h[CI_*C_], s_wph_l[CI_*C_];
__device__ __align__(1024) __nv_bfloat16 s_wg_h[CI_*C_],  s_wg_l[CI_*C_];
__device__ __align__(1024) __nv_bfloat16 s_wo_h[C_*CI_],  s_wo_l[C_*CI_];
__device__ __align__(1024) __nv_bfloat16 s_thT_h[(size_t)B_*N_*CI_], s_thT_l[(size_t)B_*N_*CI_];
__device__ __align__(1024) __nv_bfloat16 s_phT_h[(size_t)B_*M_*CI_], s_phT_l[(size_t)B_*M_*CI_];
__device__ __align__(1024) __nv_bfloat16 s_g_h[(size_t)B_*CI_*M_],  s_g_l[(size_t)B_*CI_*M_];
__device__ __align__(1024) float s_scores[(size_t)B_*N_*M_];
__device__ __align__(1024) __nv_bfloat16 s_p_h[(size_t)B_*N_*M_], s_p_l[(size_t)B_*N_*M_];
__device__ __align__(1024) __nv_bfloat16 s_tT_h[(size_t)B_*N_*CI_], s_tT_l[(size_t)B_*N_*CI_];
__device__ __align__(1024) float s_yT[(size_t)B_*N_*C_];
__device__ double s_bnsum[2*C_];
__device__ float s_bnstat[2*C_];

// ======================= helpers =======================
__device__ __forceinline__ uint32_t smem_u32(const void* p){
    uint32_t a;
    asm("{ .reg .u64 t; cvta.to.shared.u64 t, %1; cvt.u32.u64 %0, t; }" : "=r"(a) : "l"(p));
    return a;
}
__device__ __forceinline__ void cpasync16(uint32_t dst, const void* src){
    asm volatile("cp.async.cg.shared.global [%0], [%1], 16;" :: "r"(dst), "l"(src));
}
__device__ __forceinline__ void ldsm4(uint32_t* r, uint32_t addr){
    asm volatile("ldmatrix.sync.aligned.m8n8.x4.shared.b16 {%0,%1,%2,%3}, [%4];"
        : "=r"(r[0]), "=r"(r[1]), "=r"(r[2]), "=r"(r[3]) : "r"(addr));
}
__device__ __forceinline__ void mma16816(float* c, const uint32_t* a, const uint32_t* b){
    asm volatile("mma.sync.aligned.m16n8k16.row.col.f32.bf16.bf16.f32 "
        "{%0,%1,%2,%3},{%4,%5,%6,%7},{%8,%9},{%0,%1,%2,%3};"
        : "+f"(c[0]), "+f"(c[1]), "+f"(c[2]), "+f"(c[3])
        : "r"(a[0]), "r"(a[1]), "r"(a[2]), "r"(a[3]), "r"(b[0]), "r"(b[1]));
}
__device__ __forceinline__ uint32_t pack_bf16(float x, float y){
    __nv_bfloat162 t;
    t.x = __float2bfloat16(x);
    t.y = __float2bfloat16(y);
    return *reinterpret_cast<uint32_t*>(&t);
}

// ======================= mma.sync GEMM =======================
// D[m][n] = sum_k A[m][k]*B[n][k] (+bias). A,B bf16 hi/lo K-major. fp32 acc.
// CTA tile 128(m) x 256(n), K-chunk 32, 8 warps (warp tile 32m x 128n), 3-stage.
#define PITCH 80
#define OFF_AH 0u
#define OFF_AL 10240u
#define OFF_BH 20480u
#define OFF_BL 40960u
#define STAGE  61440u
#define NSTAGE 3
#define GEMM_SMEM (NSTAGE*STAGE)

__device__ __forceinline__ void load_stage(uint32_t sb, int stage,
    const __nv_bfloat16* __restrict__ Ah, const __nv_bfloat16* __restrict__ Al,
    const __nv_bfloat16* __restrict__ Bh, const __nv_bfloat16* __restrict__ Bl,
    int lda, int ldb, int m0, int n0, int k0, int tid)
{
    uint32_t st = sb + (uint32_t)stage * STAGE;
    // 3072 16B granules: A hi/lo 512+512, B hi/lo 1024+1024; 12 per thread.
    #pragma unroll
    for (int it = 0; it < 12; it++) {
        int g = tid + it * 256;
        const __nv_bfloat16* src;
        uint32_t dst;
        if (g < 1024) {
            int hl = g >> 9;          // 0 AH, 1 AL
            int idx = g & 511;
            int r = idx >> 2, q = idx & 3;
            long long off = (long long)(m0 + r) * lda + k0 + q * 8;
            src = (hl == 0 ? Ah : Al) + off;
            dst = st + (hl == 0 ? OFF_AH : OFF_AL) + (uint32_t)(r * PITCH + q * 16);
        } else {
            int gb = g - 1024;
            int hl = gb >> 10;        // 0 BH, 1 BL
            int idx = gb & 1023;
            int r = idx >> 2, q = idx & 3;
            long long off = (long long)(n0 + r) * ldb + k0 + q * 8;
            src = (hl == 0 ? Bh : Bl) + off;
            dst = st + (hl == 0 ? OFF_BH : OFF_BL) + (uint32_t)(r * PITCH + q * 16);
        }
        cpasync16(dst, src);
    }
}

__device__ __forceinline__ void compute_chunk(uint32_t sb, int stage,
                                              int wm, int wn, int lane,
                                              float acc[2][16][4])
{
    uint32_t st = sb + (uint32_t)stage * STAGE;
    uint32_t aBaseH = st + OFF_AH + (uint32_t)(wm * 32) * PITCH;
    uint32_t aBaseL = st + OFF_AL + (uint32_t)(wm * 32) * PITCH;
    uint32_t bBaseH = st + OFF_BH + (uint32_t)(wn * 128) * PITCH;
    uint32_t bBaseL = st + OFF_BL + (uint32_t)(wn * 128) * PITCH;
    int l15 = lane & 15;
    int lh = lane >> 4;
    int bn_off = ((lane >> 4) & 1) * 8 + (lane & 7);
    int bhalf = (lane >> 3) & 1;

    #pragma unroll
    for (int s = 0; s < 2; s++) {
        uint32_t aoff = (uint32_t)(s * 32 + lh * 16);
        uint32_t aH[2][4], aL[2][4];
        ldsm4(aH[0], aBaseH + (uint32_t)(l15) * PITCH + aoff);
        ldsm4(aH[1], aBaseH + (uint32_t)(16 + l15) * PITCH + aoff);
        ldsm4(aL[0], aBaseL + (uint32_t)(l15) * PITCH + aoff);
        ldsm4(aL[1], aBaseL + (uint32_t)(16 + l15) * PITCH + aoff);

        // process 128 n-cols in two halves of 64 to bound register pressure
        #pragma unroll
        for (int h = 0; h < 2; h++) {
            uint32_t bH[8][2], bL[8][2];
            #pragma unroll
            for (int p = 0; p < 4; p++) {
                uint32_t addr = (uint32_t)(((h * 4 + p) * 16 + bn_off) * PITCH + s * 32 + bhalf * 16);
                uint32_t r4[4];
                ldsm4(r4, bBaseH + addr);
                bH[2*p][0] = r4[0]; bH[2*p][1] = r4[1];
                bH[2*p+1][0] = r4[2]; bH[2*p+1][1] = r4[3];
                ldsm4(r4, bBaseL + addr);
                bL[2*p][0] = r4[0]; bL[2*p][1] = r4[1];
                bL[2*p+1][0] = r4[2]; bL[2*p+1][1] = r4[3];
            }
            // 3 product passes; 16 independent accumulators per pass
            #pragma unroll
            for (int mt = 0; mt < 2; mt++)
                #pragma unroll
                for (int nt = 0; nt < 8; nt++)
                    mma16816(acc[mt][h*8+nt], aH[mt], bH[nt]);
            #pragma unroll
            for (int mt = 0; mt < 2; mt++)
                #pragma unroll
                for (int nt = 0; nt < 8; nt++)
                    mma16816(acc[mt][h*8+nt], aH[mt], bL[nt]);
            #pragma unroll
            for (int mt = 0; mt < 2; mt++)
                #pragma unroll
                for (int nt = 0; nt < 8; nt++)
                    mma16816(acc[mt][h*8+nt], aL[mt], bH[nt]);
        }
    }
}

// OUTMODE 0: fp32 to Cf ; OUTMODE 1: split bf16 to Ch/Cl
template<int OUTMODE>
__global__ void __launch_bounds__(256, 1)
mm_gemm(const __nv_bfloat16* __restrict__ Ah, const __nv_bfloat16* __restrict__ Al,
        long long a_bs, int lda,
        const __nv_bfloat16* __restrict__ Bh, const __nv_bfloat16* __restrict__ Bl,
        long long b_bs, int ldb,
        float* __restrict__ Cf, __nv_bfloat16* __restrict__ Ch, __nv_bfloat16* __restrict__ Cl,
        long long c_bs, int ldc,
        int K, const float* __restrict__ bias, int bias_mode)
{
    extern __shared__ char sm[];
    uint32_t sb = smem_u32(sm);
    int tid = threadIdx.x;
    int wid = tid >> 5, lane = tid & 31;
    int wm = wid & 3, wn = wid >> 2;        // wm 0..3 (m), wn 0..1 (n)
    int z = blockIdx.z;
    int m0 = blockIdx.y * 128;
    int n0 = blockIdx.x * 256;

    const __nv_bfloat16* pAh = Ah + (long long)z * a_bs;
    const __nv_bfloat16* pAl = Al + (long long)z * a_bs;
    const __nv_bfloat16* pBh = Bh + (long long)z * b_bs;
    const __nv_bfloat16* pBl = Bl + (long long)z * b_bs;

    float acc[2][16][4] = {};
    int nc = K / 32;

    // prologue: fill 2 stages
    load_stage(sb, 0, pAh, pAl, pBh, pBl, lda, ldb, m0, n0, 0, tid);
    asm volatile("cp.async.commit_group;" ::: "memory");
    if (nc > 1)
        load_stage(sb, 1, pAh, pAl, pBh, pBl, lda, ldb, m0, n0, 32, tid);
    asm volatile("cp.async.commit_group;" ::: "memory");

    int stage = 0, nstage = 2 % NSTAGE;
    for (int i = 0; i < nc; i++) {
        asm volatile("cp.async.wait_group 1;" ::: "memory");  // stage i ready
        __syncthreads();
        if (i + 2 < nc)
            load_stage(sb, nstage, pAh, pAl, pBh, pBl, lda, ldb, m0, n0, (i + 2) * 32, tid);
        asm volatile("cp.async.commit_group;" ::: "memory");
        compute_chunk(sb, stage, wm, wn, lane, acc);
        stage = (stage + 1 == NSTAGE) ? 0 : stage + 1;
        nstage = (nstage + 1 == NSTAGE) ? 0 : nstage + 1;
    }

    // epilogue
    int r = lane >> 2, cg = lane & 3;
    int mb = m0 + wm * 32, nb = n0 + wn * 128;
    #pragma unroll
    for (int mt = 0; mt < 2; mt++) {
        int mrow = mb + mt * 16 + r;
        float br0 = 0.0f, br1 = 0.0f;
        if (bias_mode == 1) { br0 = __ldg(&bias[mrow]); br1 = __ldg(&bias[mrow + 8]); }
        #pragma unroll
        for (int nt = 0; nt < 16; nt++) {
            int col = nb + nt * 8 + cg * 2;
            float bc0 = 0.0f, bc1 = 0.0f;
            if (bias_mode == 2) { bc0 = __ldg(&bias[col]); bc1 = __ldg(&bias[col + 1]); }
            float v00 = acc[mt][nt][0] + br0 + bc0;
            float v01 = acc[mt][nt][1] + br0 + bc1;
            float v10 = acc[mt][nt][2] + br1 + bc0;
            float v11 = acc[mt][nt][3] + br1 + bc1;
            long long o0 = (long long)z * c_bs + (long long)mrow * ldc + col;
            long long o1 = o0 + (long long)8 * ldc;
            if (OUTMODE == 0) {
                *reinterpret_cast<float2*>(Cf + o0) = make_float2(v00, v01);
                *reinterpret_cast<float2*>(Cf + o1) = make_float2(v10, v11);
            } else {
                __nv_bfloat16 h00 = __float2bfloat16(v00), h01 = __float2bfloat16(v01);
                __nv_bfloat16 h10 = __float2bfloat16(v10), h11 = __float2bfloat16(v11);
                *reinterpret_cast<uint32_t*>(Ch + o0) = pack_bf16(v00, v01);
                *reinterpret_cast<uint32_t*>(Ch + o1) = pack_bf16(v10, v11);
                *reinterpret_cast<uint32_t*>(Cl + o0) =
                    pack_bf16(v00 - __bfloat162float(h00), v01 - __bfloat162float(h01));
                *reinterpret_cast<uint32_t*>(Cl + o1) =
                    pack_bf16(v10 - __bfloat162float(h10), v11 - __bfloat162float(h11));
            }
        }
    }
}

// ======================= conversions =======================
__global__ void split_kernel(const float* __restrict__ src, __nv_bfloat16* __restrict__ h,
                             __nv_bfloat16* __restrict__ l, int n) {
    int i = blockIdx.x * blockDim.x + threadIdx.x;
    if (i < n) {
        float v = src[i];
        __nv_bfloat16 hh = __float2bfloat16(v);
        h[i] = hh;
        l[i] = __float2bfloat16(v - __bfloat162float(hh));
    }
}

// src [z][R][CC] -> dst [z][CC][R] split bf16
__global__ void transpose_split_kernel(const float* __restrict__ src,
                                       __nv_bfloat16* __restrict__ dh, __nv_bfloat16* __restrict__ dl,
                                       int R, int CC) {
    __shared__ float tile[32][33];
    int z = blockIdx.z;
    int c0 = blockIdx.x * 32;
    int r0 = blockIdx.y * 32;
    int tx = threadIdx.x, ty = threadIdx.y;
    const float* s = src + (long long)z * R * CC;
    #pragma unroll
    for (int i = 0; i < 4; i++)
        tile[ty + i * 8][tx] = s[(long long)(r0 + ty + i * 8) * CC + c0 + tx];
    __syncthreads();
    __nv_bfloat16* oh = dh + (long long)z * R * CC;
    __nv_bfloat16* ol = dl + (long long)z * R * CC;
    #pragma unroll
    for (int i = 0; i < 4; i++) {
        float v = tile[tx][ty + i * 8];
        __nv_bfloat16 hh = __float2bfloat16(v);
        long long o = (long long)(c0 + ty + i * 8) * R + r0 + tx;
        oh[o] = hh;
        ol[o] = __float2bfloat16(v - __bfloat162float(hh));
    }
}

// x [z][C][64x64] -> pooled transposed split [z][m=1024][c=1024]
__global__ void pool_transpose_split_kernel(const float* __restrict__ x,
                                            __nv_bfloat16* __restrict__ dh, __nv_bfloat16* __restrict__ dl) {
    __shared__ float tile[32][33];
    int z = blockIdx.z;
    int m0 = blockIdx.x * 32;
    int c0 = blockIdx.y * 32;
    int tx = threadIdx.x, ty = threadIdx.y;
    #pragma unroll
    for (int i = 0; i < 4; i++) {
        int c = c0 + ty + i * 8;
        int m = m0 + tx;
        int pi = m >> 5, pj = m & 31;
        const float* b = x + ((long long)z * C_ + c) * 4096 + (pi * 2) * 64 + pj * 2;
        float v = fmaxf(fmaxf(b[0], b[1]), fmaxf(b[64], b[65]));
        tile[ty + i * 8][tx] = v;
    }
    __syncthreads();
    #pragma unroll
    for (int i = 0; i < 4; i++) {
        float v = tile[tx][ty + i * 8];
        __nv_bfloat16 hh = __float2bfloat16(v);
        long long o = ((long long)z * M_ + m0 + ty + i * 8) * C_ + c0 + tx;
        dh[o] = hh;
        dl[o] = __float2bfloat16(v - __bfloat162float(hh));
    }
}

// ======================= softmax (scaled) + split =======================
__global__ void softmax_split_kernel(const float* __restrict__ s,
                                     __nv_bfloat16* __restrict__ ph, __nv_bfloat16* __restrict__ pl,
                                     float scale) {
    const float* row = s + (size_t)blockIdx.x * M_;
    int tid = threadIdx.x;
    float v[4];
    float mx = -1e30f;
    #pragma unroll
    for (int i = 0; i < 4; i++) { v[i] = row[tid + 256 * i] * scale; mx = fmaxf(mx, v[i]); }
    __shared__ float red[8], red2[8];
    #pragma unroll
    for (int o = 16; o > 0; o >>= 1) mx = fmaxf(mx, __shfl_xor_sync(0xffffffffu, mx, o));
    if ((tid & 31) == 0) red[tid >> 5] = mx;
    __syncthreads();
    mx = fmaxf(fmaxf(fmaxf(red[0], red[1]), fmaxf(red[2], red[3])),
               fmaxf(fmaxf(red[4], red[5]), fmaxf(red[6], red[7])));
    float sum = 0.0f;
    #pragma unroll
    for (int i = 0; i < 4; i++) { v[i] = __expf(v[i] - mx); sum += v[i]; }
    #pragma unroll
    for (int o = 16; o > 0; o >>= 1) sum += __shfl_xor_sync(0xffffffffu, sum, o);
    if ((tid & 31) == 0) red2[tid >> 5] = sum;
    __syncthreads();
    sum = (red2[0] + red2[1]) + (red2[2] + red2[3]) + (red2[4] + red2[5]) + (red2[6] + red2[7]);
    float inv = 1.0f / sum;
    size_t base = (size_t)blockIdx.x * M_;
    #pragma unroll
    for (int i = 0; i < 4; i++) {
        float p = v[i] * inv;
        __nv_bfloat16 hh = __float2bfloat16(p);
        ph[base + tid + 256 * i] = hh;
        pl[base + tid + 256 * i] = __float2bfloat16(p - __bfloat162float(hh));
    }
}

// ======================= BatchNorm =======================
__global__ void bn_zero_kernel(double* sums) {
    int i = blockIdx.x * blockDim.x + threadIdx.x;
    if (i < 2 * C_) sums[i] = 0.0;
}
__global__ void bn_stats_kernel(const float* __restrict__ yT, double* __restrict__ sums) {
    int tid = threadIdx.x;
    int c = blockIdx.x * 128 + (tid & 127);
    int half = tid >> 7;
    int r0 = blockIdx.y * 1024 + half * 512;
    float s = 0.0f, s2 = 0.0f;
    for (int r = 0; r < 512; r++) {
        float v = yT[(long long)(r0 + r) * C_ + c];
        s += v; s2 += v * v;
    }
    atomicAdd(&sums[c], (double)s);
    atomicAdd(&sums[C_ + c], (double)s2);
}
__global__ void bn_final_kernel(const double* __restrict__ sums, float* __restrict__ stat) {
    int c = blockIdx.x * blockDim.x + threadIdx.x;
    if (c < C_) {
        double cnt = (double)B_ * N_;
        double mean = sums[c] / cnt;
        double var = sums[C_ + c] / cnt - mean * mean;
        stat[c] = (float)mean;
        stat[C_ + c] = rsqrtf((float)var + 1e-5f);
    }
}
__global__ void bn_apply_kernel(const float* __restrict__ yT, const float* __restrict__ x,
                                const float* __restrict__ stat,
                                const float* __restrict__ gamma, const float* __restrict__ beta,
                                float* __restrict__ out) {
    __shared__ float tile[32][33];
    int z = blockIdx.z;
    int n0 = blockIdx.x * 32;
    int c0 = blockIdx.y * 32;
    int tx = threadIdx.x, ty = threadIdx.y;
    #pragma unroll
    for (int i = 0; i < 4; i++)
        tile[ty + i * 8][tx] = yT[((long long)z * N_ + n0 + ty + i * 8) * C_ + c0 + tx];
    __syncthreads();
    #pragma unroll
    for (int i = 0; i < 4; i++) {
        int c = c0 + ty + i * 8;
        int n = n0 + tx;
        float mean = stat[c], rstd = stat[C_ + c];
        long long o = ((long long)z * C_ + c) * N_ + n;
        out[o] = (tile[tx][ty + i * 8] - mean) * rstd * gamma[c] + beta[c] + x[o];
    }
}

// ======================= launch =======================
extern "C" void kernel_launch(void* const* d_in, const int* in_sizes, int n_in,
                              void* d_out, int out_size) {
    const float* x       = (const float*)d_in[0];
    const float* w_theta = (const float*)d_in[1];
    const float* b_theta = (const float*)d_in[2];
    const float* w_phi   = (const float*)d_in[3];
    const float* b_phi   = (const float*)d_in[4];
    const float* w_g     = (const float*)d_in[5];
    const float* b_g     = (const float*)d_in[6];
    const float* w_out   = (const float*)d_in[7];
    const float* b_out   = (const float*)d_in[8];
    const float* gamma   = (const float*)d_in[9];
    const float* beta    = (const float*)d_in[10];
    float* out = (float*)d_out;

    cudaFuncSetAttribute(mm_gemm<0>, cudaFuncAttributeMaxDynamicSharedMemorySize, GEMM_SMEM);
    cudaFuncSetAttribute(mm_gemm<1>, cudaFuncAttributeMaxDynamicSharedMemorySize, GEMM_SMEM);

    __nv_bfloat16 *xT_h, *xT_l, *pxT_h, *pxT_l;
    __nv_bfloat16 *wth_h, *wth_l, *wph_h, *wph_l, *wg_h, *wg_l, *wo_h, *wo_l;
    __nv_bfloat16 *thT_h, *thT_l, *phT_h, *phT_l, *g_h, *g_l, *p_h, *p_l, *tT_h, *tT_l;
    float *scores, *yT, *bnstat;
    double *bnsum;
    cudaGetSymbolAddress((void**)&xT_h, s_xT_h);   cudaGetSymbolAddress((void**)&xT_l, s_xT_l);
    cudaGetSymbolAddress((void**)&pxT_h, s_pxT_h); cudaGetSymbolAddress((void**)&pxT_l, s_pxT_l);
    cudaGetSymbolAddress((void**)&wth_h, s_wth_h); cudaGetSymbolAddress((void**)&wth_l, s_wth_l);
    cudaGetSymbolAddress((void**)&wph_h, s_wph_h); cudaGetSymbolAddress((void**)&wph_l, s_wph_l);
    cudaGetSymbolAddress((void**)&wg_h, s_wg_h);   cudaGetSymbolAddress((void**)&wg_l, s_wg_l);
    cudaGetSymbolAddress((void**)&wo_h, s_wo_h);   cudaGetSymbolAddress((void**)&wo_l, s_wo_l);
    cudaGetSymbolAddress((void**)&thT_h, s_thT_h); cudaGetSymbolAddress((void**)&thT_l, s_thT_l);
    cudaGetSymbolAddress((void**)&phT_h, s_phT_h); cudaGetSymbolAddress((void**)&phT_l, s_phT_l);
    cudaGetSymbolAddress((void**)&g_h, s_g_h);     cudaGetSymbolAddress((void**)&g_l, s_g_l);
    cudaGetSymbolAddress((void**)&p_h, s_p_h);     cudaGetSymbolAddress((void**)&p_l, s_p_l);
    cudaGetSymbolAddress((void**)&tT_h, s_tT_h);   cudaGetSymbolAddress((void**)&tT_l, s_tT_l);
    cudaGetSymbolAddress((void**)&scores, s_scores);
    cudaGetSymbolAddress((void**)&yT, s_yT);
    cudaGetSymbolAddress((void**)&bnsum, s_bnsum);
    cudaGetSymbolAddress((void**)&bnstat, s_bnstat);

    dim3 tb(32, 8);

    split_kernel<<<(CI_ * C_ + 255) / 256, 256>>>(w_theta, wth_h, wth_l, CI_ * C_);
    split_kernel<<<(CI_ * C_ + 255) / 256, 256>>>(w_phi, wph_h, wph_l, CI_ * C_);
    split_kernel<<<(CI_ * C_ + 255) / 256, 256>>>(w_g, wg_h, wg_l, CI_ * C_);
    split_kernel<<<(C_ * CI_ + 255) / 256, 256>>>(w_out, wo_h, wo_l, C_ * CI_);

    transpose_split_kernel<<<dim3(N_ / 32, C_ / 32, B_), tb>>>(x, xT_h, xT_l, C_, N_);
    pool_transpose_split_kernel<<<dim3(M_ / 32, C_ / 32, B_), tb>>>(x, pxT_h, pxT_l);

    // GEMM1: thT[n][ci] = xT @ w_theta^T ; rows=4096, cols=512, K=1024
    mm_gemm<1><<<dim3(CI_ / 256, N_ / 128, B_), 256, GEMM_SMEM>>>(
        xT_h, xT_l, (long long)N_ * C_, C_,
        wth_h, wth_l, 0, C_,
        nullptr, thT_h, thT_l, (long long)N_ * CI_, CI_,
        C_, b_theta, 2);
    // GEMM2: phT[m][ci] ; rows=1024, cols=512, K=1024
    mm_gemm<1><<<dim3(CI_ / 256, M_ / 128, B_), 256, GEMM_SMEM>>>(
        pxT_h, pxT_l, (long long)M_ * C_, C_,
        wph_h, wph_l, 0, C_,
        nullptr, phT_h, phT_l, (long long)M_ * CI_, CI_,
        C_, b_phi, 2);
    // GEMM3: g[ci][m] ; rows=512, cols=1024, K=1024
    mm_gemm<1><<<dim3(M_ / 256, CI_ / 128, B_), 256, GEMM_SMEM>>>(
        wg_h, wg_l, 0, C_,
        pxT_h, pxT_l, (long long)M_ * C_, C_,
        nullptr, g_h, g_l, (long long)CI_ * M_, M_,
        C_, b_g, 1);
    // GEMM4: scores[n][m] ; rows=4096, cols=1024, K=512
    mm_gemm<0><<<dim3(M_ / 256, N_ / 128, B_), 256, GEMM_SMEM>>>(
        thT_h, thT_l, (long long)N_ * CI_, CI_,
        phT_h, phT_l, (long long)M_ * CI_, CI_,
        scores, nullptr, nullptr, (long long)N_ * M_, M_,
        CI_, nullptr, 0);
    softmax_split_kernel<<<B_ * N_, 256>>>(scores, p_h, p_l, rsqrtf((float)CI_));
    // GEMM5: tT[n][ci] = p @ g^T ; rows=4096, cols=512, K=1024
    mm_gemm<1><<<dim3(CI_ / 256, N_ / 128, B_), 256, GEMM_SMEM>>>(
        p_h, p_l, (long long)N_ * M_, M_,
        g_h, g_l, (long long)CI_ * M_, M_,
        nullptr, tT_h, tT_l, (long long)N_ * CI_, CI_,
        M_, nullptr, 0);
    // GEMM6: yT[n][c] = tT @ w_out^T ; rows=4096, cols=1024, K=512
    mm_gemm<0><<<dim3(C_ / 256, N_ / 128, B_), 256, GEMM_SMEM>>>(
        tT_h, tT_l, (long long)N_ * CI_, CI_,
        wo_h, wo_l, 0, CI_,
        yT, nullptr, nullptr, (long long)N_ * C_, C_,
        CI_, b_out, 2);

    bn_zero_kernel<<<8, 256>>>(bnsum);
    bn_stats_kernel<<<dim3(C_ / 128, 32), 256>>>(yT, bnsum);
    bn_final_kernel<<<4, 256>>>(bnsum, bnstat);
    bn_apply_kernel<<<dim3(N_ / 32, C_ / 32, B_), tb>>>(yT, x, bnstat, gamma, beta, out);
}

// round 8
// speedup vs baseline: 7.3490x; 1.3486x over previous
#include <cuda_runtime.h>
#include <cuda_bf16.h>
#include <cuda_fp16.h>
#include <cstdint>
#include <math.h>

#define B_  8
#define C_  1024
#define CI_ 512
#define N_  4096
#define M_  1024

// ======================= scratch (device globals) =======================
__device__ __align__(1024) __half        s_xT[(size_t)B_*N_*C_];     // [b][n][c] fp16
__device__ __align__(1024) __half        s_pxT[(size_t)B_*M_*C_];    // [b][m][c] fp16
__device__ __align__(1024) __half        s_wth[CI_*C_];
__device__ __align__(1024) __half        s_wph[CI_*C_];
__device__ __align__(1024) __half        s_wg[CI_*C_];
__device__ __align__(1024) __nv_bfloat16 s_wo_h[C_*CI_], s_wo_l[C_*CI_];
__device__ __align__(1024) __half        s_thT[(size_t)B_*N_*CI_];   // [b][n][ci] fp16
__device__ __align__(1024) __half        s_phT[(size_t)B_*M_*CI_];   // [b][m][ci] fp16
__device__ __align__(1024) __nv_bfloat16 s_g_h[(size_t)B_*CI_*M_], s_g_l[(size_t)B_*CI_*M_];
__device__ __align__(1024) float  s_scores[(size_t)B_*N_*M_];
__device__ __align__(1024) __nv_bfloat16 s_p_h[(size_t)B_*N_*M_], s_p_l[(size_t)B_*N_*M_];
__device__ __align__(1024) __nv_bfloat16 s_tT_h[(size_t)B_*N_*CI_], s_tT_l[(size_t)B_*N_*CI_];
__device__ __align__(1024) float  s_yT[(size_t)B_*N_*C_];
__device__ double s_bnsum[2*C_];
__device__ float  s_bnstat[2*C_];

// ======================= helpers =======================
__device__ __forceinline__ uint32_t smem_u32(const void* p){
    uint32_t a;
    asm("{ .reg .u64 t; cvta.to.shared.u64 t, %1; cvt.u32.u64 %0, t; }" : "=r"(a) : "l"(p));
    return a;
}
__device__ __forceinline__ void cpasync16(uint32_t dst, const void* src){
    asm volatile("cp.async.cg.shared.global [%0], [%1], 16;" :: "r"(dst), "l"(src));
}
__device__ __forceinline__ void ldsm4(uint32_t* r, uint32_t addr){
    asm volatile("ldmatrix.sync.aligned.m8n8.x4.shared.b16 {%0,%1,%2,%3}, [%4];"
        : "=r"(r[0]), "=r"(r[1]), "=r"(r[2]), "=r"(r[3]) : "r"(addr));
}
__device__ __forceinline__ void mma_bf(float* c, const uint32_t* a, const uint32_t* b){
    asm volatile("mma.sync.aligned.m16n8k16.row.col.f32.bf16.bf16.f32 "
        "{%0,%1,%2,%3},{%4,%5,%6,%7},{%8,%9},{%0,%1,%2,%3};"
        : "+f"(c[0]), "+f"(c[1]), "+f"(c[2]), "+f"(c[3])
        : "r"(a[0]), "r"(a[1]), "r"(a[2]), "r"(a[3]), "r"(b[0]), "r"(b[1]));
}
__device__ __forceinline__ void mma_hf(float* c, const uint32_t* a, const uint32_t* b){
    asm volatile("mma.sync.aligned.m16n8k16.row.col.f32.f16.f16.f32 "
        "{%0,%1,%2,%3},{%4,%5,%6,%7},{%8,%9},{%0,%1,%2,%3};"
        : "+f"(c[0]), "+f"(c[1]), "+f"(c[2]), "+f"(c[3])
        : "r"(a[0]), "r"(a[1]), "r"(a[2]), "r"(a[3]), "r"(b[0]), "r"(b[1]));
}
__device__ __forceinline__ uint32_t pack_bf16(float x, float y){
    __nv_bfloat162 t;
    t.x = __float2bfloat16(x);
    t.y = __float2bfloat16(y);
    return *reinterpret_cast<uint32_t*>(&t);
}
__device__ __forceinline__ uint32_t pack_h2(float x, float y){
    __half2 t = __floats2half2_rn(x, y);
    return *reinterpret_cast<uint32_t*>(&t);
}

#define PITCH 80

// ======================= fp16 single-product GEMM (logit path) =======================
// D[m][n] = sum_k A[m][k]*B[n][k] (+bias). CTA 128x256, Kc=32, 8 warps, 4-stage.
#define HF_OFF_A  0u
#define HF_OFF_B  10240u
#define HF_STAGE  30720u
#define HF_NSTAGE 4
#define HF_SMEM (HF_NSTAGE*HF_STAGE)

__device__ __forceinline__ void hf_load_stage(uint32_t sb, int stage,
    const __half* __restrict__ A, const __half* __restrict__ Bm,
    int lda, int ldb, int m0, int n0, int k0, int tid)
{
    uint32_t st = sb + (uint32_t)stage * HF_STAGE;
    #pragma unroll
    for (int it = 0; it < 6; it++) {
        int g = tid + it * 256;
        const __half* src;
        uint32_t dst;
        if (g < 512) {
            int r = g >> 2, q = g & 3;
            src = A + (long long)(m0 + r) * lda + k0 + q * 8;
            dst = st + HF_OFF_A + (uint32_t)(r * PITCH + q * 16);
        } else {
            int gb = g - 512;
            int r = gb >> 2, q = gb & 3;
            src = Bm + (long long)(n0 + r) * ldb + k0 + q * 8;
            dst = st + HF_OFF_B + (uint32_t)(r * PITCH + q * 16);
        }
        cpasync16(dst, src);
    }
}

__device__ __forceinline__ void hf_compute(uint32_t sb, int stage,
                                           int wm, int wn, int lane,
                                           float acc[2][16][4])
{
    uint32_t st = sb + (uint32_t)stage * HF_STAGE;
    uint32_t aBase = st + HF_OFF_A + (uint32_t)(wm * 32) * PITCH;
    uint32_t bBase = st + HF_OFF_B + (uint32_t)(wn * 128) * PITCH;
    int l15 = lane & 15;
    int lh = lane >> 4;
    int bn_off = ((lane >> 4) & 1) * 8 + (lane & 7);
    int bhalf = (lane >> 3) & 1;

    #pragma unroll
    for (int s = 0; s < 2; s++) {
        uint32_t aoff = (uint32_t)(s * 32 + lh * 16);
        uint32_t aF[2][4];
        ldsm4(aF[0], aBase + (uint32_t)(l15) * PITCH + aoff);
        ldsm4(aF[1], aBase + (uint32_t)(16 + l15) * PITCH + aoff);

        #pragma unroll
        for (int h = 0; h < 2; h++) {
            uint32_t bF[8][2];
            #pragma unroll
            for (int p = 0; p < 4; p++) {
                uint32_t addr = (uint32_t)(((h * 4 + p) * 16 + bn_off) * PITCH + s * 32 + bhalf * 16);
                uint32_t r4[4];
                ldsm4(r4, bBase + addr);
                bF[2*p][0] = r4[0]; bF[2*p][1] = r4[1];
                bF[2*p+1][0] = r4[2]; bF[2*p+1][1] = r4[3];
            }
            #pragma unroll
            for (int mt = 0; mt < 2; mt++)
                #pragma unroll
                for (int nt = 0; nt < 8; nt++)
                    mma_hf(acc[mt][h*8+nt], aF[mt], bF[nt]);
        }
    }
}

// OUTMODE 0: fp32 to Cf ; 1: fp16 to Ch ; 2: split bf16 to Sh/Sl
template<int OUTMODE>
__global__ void __launch_bounds__(256, 1)
gemm_hf(const __half* __restrict__ A, long long a_bs, int lda,
        const __half* __restrict__ Bm, long long b_bs, int ldb,
        float* __restrict__ Cf, __half* __restrict__ Ch,
        __nv_bfloat16* __restrict__ Sh, __nv_bfloat16* __restrict__ Sl,
        long long c_bs, int ldc,
        int K, const float* __restrict__ bias, int bias_mode)
{
    extern __shared__ char sm[];
    uint32_t sb = smem_u32(sm);
    int tid = threadIdx.x;
    int wid = tid >> 5, lane = tid & 31;
    int wm = wid & 3, wn = wid >> 2;
    int z = blockIdx.z;
    int m0 = blockIdx.y * 128;
    int n0 = blockIdx.x * 256;

    const __half* pA = A + (long long)z * a_bs;
    const __half* pB = Bm + (long long)z * b_bs;

    float acc[2][16][4] = {};
    int nc = K / 32;

    #pragma unroll
    for (int s = 0; s < 3; s++) {
        if (s < nc)
            hf_load_stage(sb, s, pA, pB, lda, ldb, m0, n0, s * 32, tid);
        asm volatile("cp.async.commit_group;" ::: "memory");
    }

    for (int i = 0; i < nc; i++) {
        asm volatile("cp.async.wait_group 2;" ::: "memory");
        __syncthreads();
        if (i + 3 < nc)
            hf_load_stage(sb, (i + 3) & (HF_NSTAGE - 1), pA, pB, lda, ldb, m0, n0, (i + 3) * 32, tid);
        asm volatile("cp.async.commit_group;" ::: "memory");
        hf_compute(sb, i & (HF_NSTAGE - 1), wm, wn, lane, acc);
    }

    int r = lane >> 2, cg = lane & 3;
    int mb = m0 + wm * 32, nb = n0 + wn * 128;
    #pragma unroll
    for (int mt = 0; mt < 2; mt++) {
        int mrow = mb + mt * 16 + r;
        float br0 = 0.0f, br1 = 0.0f;
        if (bias_mode == 1) { br0 = __ldg(&bias[mrow]); br1 = __ldg(&bias[mrow + 8]); }
        #pragma unroll
        for (int nt = 0; nt < 16; nt++) {
            int col = nb + nt * 8 + cg * 2;
            float bc0 = 0.0f, bc1 = 0.0f;
            if (bias_mode == 2) { bc0 = __ldg(&bias[col]); bc1 = __ldg(&bias[col + 1]); }
            float v00 = acc[mt][nt][0] + br0 + bc0;
            float v01 = acc[mt][nt][1] + br0 + bc1;
            float v10 = acc[mt][nt][2] + br1 + bc0;
            float v11 = acc[mt][nt][3] + br1 + bc1;
            long long o0 = (long long)z * c_bs + (long long)mrow * ldc + col;
            long long o1 = o0 + (long long)8 * ldc;
            if (OUTMODE == 0) {
                *reinterpret_cast<float2*>(Cf + o0) = make_float2(v00, v01);
                *reinterpret_cast<float2*>(Cf + o1) = make_float2(v10, v11);
            } else if (OUTMODE == 1) {
                *reinterpret_cast<uint32_t*>(Ch + o0) = pack_h2(v00, v01);
                *reinterpret_cast<uint32_t*>(Ch + o1) = pack_h2(v10, v11);
            } else {
                __nv_bfloat16 h00 = __float2bfloat16(v00), h01 = __float2bfloat16(v01);
                __nv_bfloat16 h10 = __float2bfloat16(v10), h11 = __float2bfloat16(v11);
                *reinterpret_cast<uint32_t*>(Sh + o0) = pack_bf16(v00, v01);
                *reinterpret_cast<uint32_t*>(Sh + o1) = pack_bf16(v10, v11);
                *reinterpret_cast<uint32_t*>(Sl + o0) =
                    pack_bf16(v00 - __bfloat162float(h00), v01 - __bfloat162float(h01));
                *reinterpret_cast<uint32_t*>(Sl + o1) =
                    pack_bf16(v10 - __bfloat162float(h10), v11 - __bfloat162float(h11));
            }
        }
    }
}

// ======================= bf16 3-product GEMM (post-softmax path) =======================
#define BF_OFF_A  0u
#define BF_OFF_AL 10240u
#define BF_OFF_B  20480u
#define BF_OFF_BL 40960u
#define BF_STAGE  61440u
#define BF_NSTAGE 3
#define BF_SMEM (BF_NSTAGE*BF_STAGE)

__device__ __forceinline__ void bf_load_stage(uint32_t sb, int stage,
    const __nv_bfloat16* __restrict__ Ah, const __nv_bfloat16* __restrict__ Al,
    const __nv_bfloat16* __restrict__ Bh, const __nv_bfloat16* __restrict__ Bl,
    int lda, int ldb, int m0, int n0, int k0, int tid)
{
    uint32_t st = sb + (uint32_t)stage * BF_STAGE;
    #pragma unroll
    for (int it = 0; it < 12; it++) {
        int g = tid + it * 256;
        const __nv_bfloat16* src;
        uint32_t dst;
        if (g < 1024) {
            int hl = g >> 9;
            int idx = g & 511;
            int r = idx >> 2, q = idx & 3;
            long long off = (long long)(m0 + r) * lda + k0 + q * 8;
            src = (hl == 0 ? Ah : Al) + off;
            dst = st + (hl == 0 ? BF_OFF_A : BF_OFF_AL) + (uint32_t)(r * PITCH + q * 16);
        } else {
            int gb = g - 1024;
            int hl = gb >> 10;
            int idx = gb & 1023;
            int r = idx >> 2, q = idx & 3;
            long long off = (long long)(n0 + r) * ldb + k0 + q * 8;
            src = (hl == 0 ? Bh : Bl) + off;
            dst = st + (hl == 0 ? BF_OFF_B : BF_OFF_BL) + (uint32_t)(r * PITCH + q * 16);
        }
        cpasync16(dst, src);
    }
}

__device__ __forceinline__ void bf_compute(uint32_t sb, int stage,
                                           int wm, int wn, int lane,
                                           float acc[2][16][4])
{
    uint32_t st = sb + (uint32_t)stage * BF_STAGE;
    uint32_t aBaseH = st + BF_OFF_A + (uint32_t)(wm * 32) * PITCH;
    uint32_t aBaseL = st + BF_OFF_AL + (uint32_t)(wm * 32) * PITCH;
    uint32_t bBaseH = st + BF_OFF_B + (uint32_t)(wn * 128) * PITCH;
    uint32_t bBaseL = st + BF_OFF_BL + (uint32_t)(wn * 128) * PITCH;
    int l15 = lane & 15;
    int lh = lane >> 4;
    int bn_off = ((lane >> 4) & 1) * 8 + (lane & 7);
    int bhalf = (lane >> 3) & 1;

    #pragma unroll
    for (int s = 0; s < 2; s++) {
        uint32_t aoff = (uint32_t)(s * 32 + lh * 16);
        uint32_t aH[2][4], aL[2][4];
        ldsm4(aH[0], aBaseH + (uint32_t)(l15) * PITCH + aoff);
        ldsm4(aH[1], aBaseH + (uint32_t)(16 + l15) * PITCH + aoff);
        ldsm4(aL[0], aBaseL + (uint32_t)(l15) * PITCH + aoff);
        ldsm4(aL[1], aBaseL + (uint32_t)(16 + l15) * PITCH + aoff);

        #pragma unroll
        for (int h = 0; h < 2; h++) {
            uint32_t bH[8][2], bL[8][2];
            #pragma unroll
            for (int p = 0; p < 4; p++) {
                uint32_t addr = (uint32_t)(((h * 4 + p) * 16 + bn_off) * PITCH + s * 32 + bhalf * 16);
                uint32_t r4[4];
                ldsm4(r4, bBaseH + addr);
                bH[2*p][0] = r4[0]; bH[2*p][1] = r4[1];
                bH[2*p+1][0] = r4[2]; bH[2*p+1][1] = r4[3];
                ldsm4(r4, bBaseL + addr);
                bL[2*p][0] = r4[0]; bL[2*p][1] = r4[1];
                bL[2*p+1][0] = r4[2]; bL[2*p+1][1] = r4[3];
            }
            #pragma unroll
            for (int mt = 0; mt < 2; mt++)
                #pragma unroll
                for (int nt = 0; nt < 8; nt++)
                    mma_bf(acc[mt][h*8+nt], aH[mt], bH[nt]);
            #pragma unroll
            for (int mt = 0; mt < 2; mt++)
                #pragma unroll
                for (int nt = 0; nt < 8; nt++)
                    mma_bf(acc[mt][h*8+nt], aH[mt], bL[nt]);
            #pragma unroll
            for (int mt = 0; mt < 2; mt++)
                #pragma unroll
                for (int nt = 0; nt < 8; nt++)
                    mma_bf(acc[mt][h*8+nt], aL[mt], bH[nt]);
        }
    }
}

// OUTMODE 0: fp32 to Cf ; 1: split bf16 to Ch/Cl
template<int OUTMODE>
__global__ void __launch_bounds__(256, 1)
gemm_bf(const __nv_bfloat16* __restrict__ Ah, const __nv_bfloat16* __restrict__ Al,
        long long a_bs, int lda,
        const __nv_bfloat16* __restrict__ Bh, const __nv_bfloat16* __restrict__ Bl,
        long long b_bs, int ldb,
        float* __restrict__ Cf, __nv_bfloat16* __restrict__ Ch, __nv_bfloat16* __restrict__ Cl,
        long long c_bs, int ldc,
        int K, const float* __restrict__ bias, int bias_mode)
{
    extern __shared__ char sm[];
    uint32_t sb = smem_u32(sm);
    int tid = threadIdx.x;
    int wid = tid >> 5, lane = tid & 31;
    int wm = wid & 3, wn = wid >> 2;
    int z = blockIdx.z;
    int m0 = blockIdx.y * 128;
    int n0 = blockIdx.x * 256;

    const __nv_bfloat16* pAh = Ah + (long long)z * a_bs;
    const __nv_bfloat16* pAl = Al + (long long)z * a_bs;
    const __nv_bfloat16* pBh = Bh + (long long)z * b_bs;
    const __nv_bfloat16* pBl = Bl + (long long)z * b_bs;

    float acc[2][16][4] = {};
    int nc = K / 32;

    bf_load_stage(sb, 0, pAh, pAl, pBh, pBl, lda, ldb, m0, n0, 0, tid);
    asm volatile("cp.async.commit_group;" ::: "memory");
    if (nc > 1)
        bf_load_stage(sb, 1, pAh, pAl, pBh, pBl, lda, ldb, m0, n0, 32, tid);
    asm volatile("cp.async.commit_group;" ::: "memory");

    int stage = 0, nstage = 2 % BF_NSTAGE;
    for (int i = 0; i < nc; i++) {
        asm volatile("cp.async.wait_group 1;" ::: "memory");
        __syncthreads();
        if (i + 2 < nc)
            bf_load_stage(sb, nstage, pAh, pAl, pBh, pBl, lda, ldb, m0, n0, (i + 2) * 32, tid);
        asm volatile("cp.async.commit_group;" ::: "memory");
        bf_compute(sb, stage, wm, wn, lane, acc);
        stage = (stage + 1 == BF_NSTAGE) ? 0 : stage + 1;
        nstage = (nstage + 1 == BF_NSTAGE) ? 0 : nstage + 1;
    }

    int r = lane >> 2, cg = lane & 3;
    int mb = m0 + wm * 32, nb = n0 + wn * 128;
    #pragma unroll
    for (int mt = 0; mt < 2; mt++) {
        int mrow = mb + mt * 16 + r;
        float br0 = 0.0f, br1 = 0.0f;
        if (bias_mode == 1) { br0 = __ldg(&bias[mrow]); br1 = __ldg(&bias[mrow + 8]); }
        #pragma unroll
        for (int nt = 0; nt < 16; nt++) {
            int col = nb + nt * 8 + cg * 2;
            float bc0 = 0.0f, bc1 = 0.0f;
            if (bias_mode == 2) { bc0 = __ldg(&bias[col]); bc1 = __ldg(&bias[col + 1]); }
            float v00 = acc[mt][nt][0] + br0 + bc0;
            float v01 = acc[mt][nt][1] + br0 + bc1;
            float v10 = acc[mt][nt][2] + br1 + bc0;
            float v11 = acc[mt][nt][3] + br1 + bc1;
            long long o0 = (long long)z * c_bs + (long long)mrow * ldc + col;
            long long o1 = o0 + (long long)8 * ldc;
            if (OUTMODE == 0) {
                *reinterpret_cast<float2*>(Cf + o0) = make_float2(v00, v01);
                *reinterpret_cast<float2*>(Cf + o1) = make_float2(v10, v11);
            } else {
                __nv_bfloat16 h00 = __float2bfloat16(v00), h01 = __float2bfloat16(v01);
                __nv_bfloat16 h10 = __float2bfloat16(v10), h11 = __float2bfloat16(v11);
                *reinterpret_cast<uint32_t*>(Ch + o0) = pack_bf16(v00, v01);
                *reinterpret_cast<uint32_t*>(Ch + o1) = pack_bf16(v10, v11);
                *reinterpret_cast<uint32_t*>(Cl + o0) =
                    pack_bf16(v00 - __bfloat162float(h00), v01 - __bfloat162float(h01));
                *reinterpret_cast<uint32_t*>(Cl + o1) =
                    pack_bf16(v10 - __bfloat162float(h10), v11 - __bfloat162float(h11));
            }
        }
    }
}

// ======================= conversions =======================
__global__ void convert_h_kernel(const float* __restrict__ src, __half* __restrict__ dst, int n) {
    int i = blockIdx.x * blockDim.x + threadIdx.x;
    if (i < n) dst[i] = __float2half_rn(src[i]);
}
__global__ void split_kernel(const float* __restrict__ src, __nv_bfloat16* __restrict__ h,
                             __nv_bfloat16* __restrict__ l, int n) {
    int i = blockIdx.x * blockDim.x + threadIdx.x;
    if (i < n) {
        float v = src[i];
        __nv_bfloat16 hh = __float2bfloat16(v);
        h[i] = hh;
        l[i] = __float2bfloat16(v - __bfloat162float(hh));
    }
}

// src [z][R][CC] -> dst [z][CC][R] fp16
__global__ void transpose_convert_kernel(const float* __restrict__ src,
                                         __half* __restrict__ dst, int R, int CC) {
    __shared__ float tile[32][33];
    int z = blockIdx.z;
    int c0 = blockIdx.x * 32;
    int r0 = blockIdx.y * 32;
    int tx = threadIdx.x, ty = threadIdx.y;
    const float* s = src + (long long)z * R * CC;
    #pragma unroll
    for (int i = 0; i < 4; i++)
        tile[ty + i * 8][tx] = s[(long long)(r0 + ty + i * 8) * CC + c0 + tx];
    __syncthreads();
    __half* o = dst + (long long)z * R * CC;
    #pragma unroll
    for (int i = 0; i < 4; i++)
        o[(long long)(c0 + ty + i * 8) * R + r0 + tx] = __float2half_rn(tile[tx][ty + i * 8]);
}

// x [z][C][64x64] -> pooled transposed fp16 [z][m][c]
__global__ void pool_transpose_kernel(const float* __restrict__ x, __half* __restrict__ dst) {
    __shared__ float tile[32][33];
    int z = blockIdx.z;
    int m0 = blockIdx.x * 32;
    int c0 = blockIdx.y * 32;
    int tx = threadIdx.x, ty = threadIdx.y;
    #pragma unroll
    for (int i = 0; i < 4; i++) {
        int c = c0 + ty + i * 8;
        int m = m0 + tx;
        int pi = m >> 5, pj = m & 31;
        const float* b = x + ((long long)z * C_ + c) * 4096 + (pi * 2) * 64 + pj * 2;
        tile[ty + i * 8][tx] = fmaxf(fmaxf(b[0], b[1]), fmaxf(b[64], b[65]));
    }
    __syncthreads();
    #pragma unroll
    for (int i = 0; i < 4; i++)
        dst[((long long)z * M_ + m0 + ty + i * 8) * C_ + c0 + tx] =
            __float2half_rn(tile[tx][ty + i * 8]);
}

// ======================= softmax (scaled) -> split bf16 =======================
__global__ void softmax_split_kernel(const float* __restrict__ s,
                                     __nv_bfloat16* __restrict__ ph, __nv_bfloat16* __restrict__ pl,
                                     float scale) {
    const float* row = s + (size_t)blockIdx.x * M_;
    int tid = threadIdx.x;
    float v[4];
    float mx = -1e30f;
    #pragma unroll
    for (int i = 0; i < 4; i++) { v[i] = row[tid + 256 * i] * scale; mx = fmaxf(mx, v[i]); }
    __shared__ float red[8], red2[8];
    #pragma unroll
    for (int o = 16; o > 0; o >>= 1) mx = fmaxf(mx, __shfl_xor_sync(0xffffffffu, mx, o));
    if ((tid & 31) == 0) red[tid >> 5] = mx;
    __syncthreads();
    mx = fmaxf(fmaxf(fmaxf(red[0], red[1]), fmaxf(red[2], red[3])),
               fmaxf(fmaxf(red[4], red[5]), fmaxf(red[6], red[7])));
    float sum = 0.0f;
    #pragma unroll
    for (int i = 0; i < 4; i++) { v[i] = __expf(v[i] - mx); sum += v[i]; }
    #pragma unroll
    for (int o = 16; o > 0; o >>= 1) sum += __shfl_xor_sync(0xffffffffu, sum, o);
    if ((tid & 31) == 0) red2[tid >> 5] = sum;
    __syncthreads();
    sum = (red2[0] + red2[1]) + (red2[2] + red2[3]) + (red2[4] + red2[5]) + (red2[6] + red2[7]);
    float inv = 1.0f / sum;
    size_t base = (size_t)blockIdx.x * M_;
    #pragma unroll
    for (int i = 0; i < 4; i++) {
        float p = v[i] * inv;
        __nv_bfloat16 hh = __float2bfloat16(p);
        ph[base + tid + 256 * i] = hh;
        pl[base + tid + 256 * i] = __float2bfloat16(p - __bfloat162float(hh));
    }
}

// ======================= BatchNorm =======================
__global__ void bn_zero_kernel(double* sums) {
    int i = blockIdx.x * blockDim.x + threadIdx.x;
    if (i < 2 * C_) sums[i] = 0.0;
}
__global__ void bn_stats_kernel(const float* __restrict__ yT, double* __restrict__ sums) {
    int tid = threadIdx.x;
    int c = blockIdx.x * 128 + (tid & 127);
    int half_ = tid >> 7;
    int r0 = blockIdx.y * 1024 + half_ * 512;
    float s = 0.0f, s2 = 0.0f;
    for (int r = 0; r < 512; r++) {
        float v = yT[(long long)(r0 + r) * C_ + c];
        s += v; s2 += v * v;
    }
    atomicAdd(&sums[c], (double)s);
    atomicAdd(&sums[C_ + c], (double)s2);
}
__global__ void bn_final_kernel(const double* __restrict__ sums, float* __restrict__ stat) {
    int c = blockIdx.x * blockDim.x + threadIdx.x;
    if (c < C_) {
        double cnt = (double)B_ * N_;
        double mean = sums[c] / cnt;
        double var = sums[C_ + c] / cnt - mean * mean;
        stat[c] = (float)mean;
        stat[C_ + c] = rsqrtf((float)var + 1e-5f);
    }
}
__global__ void bn_apply_kernel(const float* __restrict__ yT, const float* __restrict__ x,
                                const float* __restrict__ stat,
                                const float* __restrict__ gamma, const float* __restrict__ beta,
                                float* __restrict__ out) {
    __shared__ float tile[32][33];
    int z = blockIdx.z;
    int n0 = blockIdx.x * 32;
    int c0 = blockIdx.y * 32;
    int tx = threadIdx.x, ty = threadIdx.y;
    #pragma unroll
    for (int i = 0; i < 4; i++)
        tile[ty + i * 8][tx] = yT[((long long)z * N_ + n0 + ty + i * 8) * C_ + c0 + tx];
    __syncthreads();
    #pragma unroll
    for (int i = 0; i < 4; i++) {
        int c = c0 + ty + i * 8;
        int n = n0 + tx;
        float mean = stat[c], rstd = stat[C_ + c];
        long long o = ((long long)z * C_ + c) * N_ + n;
        out[o] = (tile[tx][ty + i * 8] - mean) * rstd * gamma[c] + beta[c] + x[o];
    }
}

// ======================= launch =======================
extern "C" void kernel_launch(void* const* d_in, const int* in_sizes, int n_in,
                              void* d_out, int out_size) {
    const float* x       = (const float*)d_in[0];
    const float* w_theta = (const float*)d_in[1];
    const float* b_theta = (const float*)d_in[2];
    const float* w_phi   = (const float*)d_in[3];
    const float* b_phi   = (const float*)d_in[4];
    const float* w_g     = (const float*)d_in[5];
    const float* b_g     = (const float*)d_in[6];
    const float* w_out   = (const float*)d_in[7];
    const float* b_out   = (const float*)d_in[8];
    const float* gamma   = (const float*)d_in[9];
    const float* beta    = (const float*)d_in[10];
    float* out = (float*)d_out;

    cudaFuncSetAttribute(gemm_hf<0>, cudaFuncAttributeMaxDynamicSharedMemorySize, HF_SMEM);
    cudaFuncSetAttribute(gemm_hf<1>, cudaFuncAttributeMaxDynamicSharedMemorySize, HF_SMEM);
    cudaFuncSetAttribute(gemm_hf<2>, cudaFuncAttributeMaxDynamicSharedMemorySize, HF_SMEM);
    cudaFuncSetAttribute(gemm_bf<0>, cudaFuncAttributeMaxDynamicSharedMemorySize, BF_SMEM);
    cudaFuncSetAttribute(gemm_bf<1>, cudaFuncAttributeMaxDynamicSharedMemorySize, BF_SMEM);

    __half *xT, *pxT, *wth, *wph, *wg, *thT, *phT;
    __nv_bfloat16 *wo_h, *wo_l, *g_h, *g_l, *p_h, *p_l, *tT_h, *tT_l;
    float *scores, *yT, *bnstat;
    double *bnsum;
    cudaGetSymbolAddress((void**)&xT, s_xT);
    cudaGetSymbolAddress((void**)&pxT, s_pxT);
    cudaGetSymbolAddress((void**)&wth, s_wth);
    cudaGetSymbolAddress((void**)&wph, s_wph);
    cudaGetSymbolAddress((void**)&wg, s_wg);
    cudaGetSymbolAddress((void**)&wo_h, s_wo_h);  cudaGetSymbolAddress((void**)&wo_l, s_wo_l);
    cudaGetSymbolAddress((void**)&thT, s_thT);
    cudaGetSymbolAddress((void**)&phT, s_phT);
    cudaGetSymbolAddress((void**)&g_h, s_g_h);    cudaGetSymbolAddress((void**)&g_l, s_g_l);
    cudaGetSymbolAddress((void**)&p_h, s_p_h);    cudaGetSymbolAddress((void**)&p_l, s_p_l);
    cudaGetSymbolAddress((void**)&tT_h, s_tT_h);  cudaGetSymbolAddress((void**)&tT_l, s_tT_l);
    cudaGetSymbolAddress((void**)&scores, s_scores);
    cudaGetSymbolAddress((void**)&yT, s_yT);
    cudaGetSymbolAddress((void**)&bnsum, s_bnsum);
    cudaGetSymbolAddress((void**)&bnstat, s_bnstat);

    dim3 tb(32, 8);

    convert_h_kernel<<<(CI_ * C_ + 255) / 256, 256>>>(w_theta, wth, CI_ * C_);
    convert_h_kernel<<<(CI_ * C_ + 255) / 256, 256>>>(w_phi, wph, CI_ * C_);
    convert_h_kernel<<<(CI_ * C_ + 255) / 256, 256>>>(w_g, wg, CI_ * C_);
    split_kernel<<<(C_ * CI_ + 255) / 256, 256>>>(w_out, wo_h, wo_l, C_ * CI_);

    transpose_convert_kernel<<<dim3(N_ / 32, C_ / 32, B_), tb>>>(x, xT, C_, N_);
    pool_transpose_kernel<<<dim3(M_ / 32, C_ / 32, B_), tb>>>(x, pxT);

    // GEMM1 (fp16): thT[n][ci] = xT @ w_theta^T ; rows=4096, cols=512, K=1024
    gemm_hf<1><<<dim3(CI_ / 256, N_ / 128, B_), 256, HF_SMEM>>>(
        xT, (long long)N_ * C_, C_,
        wth, 0, C_,
        nullptr, thT, nullptr, nullptr, (long long)N_ * CI_, CI_,
        C_, b_theta, 2);
    // GEMM2 (fp16): phT[m][ci] ; rows=1024, cols=512, K=1024
    gemm_hf<1><<<dim3(CI_ / 256, M_ / 128, B_), 256, HF_SMEM>>>(
        pxT, (long long)M_ * C_, C_,
        wph, 0, C_,
        nullptr, phT, nullptr, nullptr, (long long)M_ * CI_, CI_,
        C_, b_phi, 2);
    // GEMM3 (fp16 -> split bf16): g[ci][m] ; rows=512, cols=1024, K=1024
    gemm_hf<2><<<dim3(M_ / 256, CI_ / 128, B_), 256, HF_SMEM>>>(
        wg, 0, C_,
        pxT, (long long)M_ * C_, C_,
        nullptr, nullptr, g_h, g_l, (long long)CI_ * M_, M_,
        C_, b_g, 1);
    // GEMM4 (fp16): scores[n][m] ; rows=4096, cols=1024, K=512
    gemm_hf<0><<<dim3(M_ / 256, N_ / 128, B_), 256, HF_SMEM>>>(
        thT, (long long)N_ * CI_, CI_,
        phT, (long long)M_ * CI_, CI_,
        scores, nullptr, nullptr, nullptr, (long long)N_ * M_, M_,
        CI_, nullptr, 0);
    softmax_split_kernel<<<B_ * N_, 256>>>(scores, p_h, p_l, rsqrtf((float)CI_));
    // GEMM5 (bf16-3): tT[n][ci] = p @ g^T ; rows=4096, cols=512, K=1024
    gemm_bf<1><<<dim3(CI_ / 256, N_ / 128, B_), 256, BF_SMEM>>>(
        p_h, p_l, (long long)N_ * M_, M_,
        g_h, g_l, (long long)CI_ * M_, M_,
        nullptr, tT_h, tT_l, (long long)N_ * CI_, CI_,
        M_, nullptr, 0);
    // GEMM6 (bf16-3): yT[n][c] = tT @ w_out^T ; rows=4096, cols=1024, K=512
    gemm_bf<0><<<dim3(C_ / 256, N_ / 128, B_), 256, BF_SMEM>>>(
        tT_h, tT_l, (long long)N_ * CI_, CI_,
        wo_h, wo_l, 0, CI_,
        yT, nullptr, nullptr, (long long)N_ * C_, C_,
        CI_, b_out, 2);

    bn_zero_kernel<<<8, 256>>>(bnsum);
    bn_stats_kernel<<<dim3(C_ / 128, 32), 256>>>(yT, bnsum);
    bn_final_kernel<<<4, 256>>>(bnsum, bnstat);
    bn_apply_kernel<<<dim3(N_ / 32, C_ / 32, B_), tb>>>(yT, x, bnstat, gamma, beta, out);
}

// round 9
// speedup vs baseline: 8.9493x; 1.2178x over previous
#include <cuda_runtime.h>
#include <cuda_fp16.h>
#include <cstdint>
#include <math.h>

#define B_  8
#define C_  1024
#define CI_ 512
#define N_  4096
#define M_  1024

// ======================= scratch (device globals) =======================
__device__ __align__(1024) __half s_xT[(size_t)B_*N_*C_];     // [b][n][c]
__device__ __align__(1024) __half s_pxT[(size_t)B_*M_*C_];    // [b][m][c]
__device__ __align__(1024) __half s_wth[CI_*C_];
__device__ __align__(1024) __half s_wph[CI_*C_];
__device__ __align__(1024) __half s_wg[CI_*C_];
__device__ __align__(1024) __half s_wo[C_*CI_];
__device__ __align__(1024) __half s_thT[(size_t)B_*N_*CI_];   // [b][n][ci]
__device__ __align__(1024) __half s_phT[(size_t)B_*M_*CI_];   // [b][m][ci]
__device__ __align__(1024) float  s_gf[(size_t)B_*CI_*M_];    // [b][ci][m] fp32
__device__ __align__(1024) __half s_gdev[(size_t)B_*CI_*M_];  // centered fp16
__device__ __align__(1024) float  s_gmean[B_*CI_];
__device__ __align__(1024) float  s_scores[(size_t)B_*N_*M_];
__device__ __align__(1024) __half s_p[(size_t)B_*N_*M_];
__device__ __align__(1024) float  s_t[(size_t)B_*N_*CI_];     // fp32 t
__device__ __align__(1024) __half s_tdev[(size_t)B_*N_*CI_];
__device__ __align__(1024) float  s_tmean[B_*CI_];
__device__ __align__(1024) float  s_ymean[B_*C_];
__device__ __align__(1024) float  s_yT[(size_t)B_*N_*C_];
__device__ double s_bnsum[2*C_];
__device__ float  s_bnstat[2*C_];

// ======================= helpers =======================
__device__ __forceinline__ uint32_t smem_u32(const void* p){
    uint32_t a;
    asm("{ .reg .u64 t; cvta.to.shared.u64 t, %1; cvt.u32.u64 %0, t; }" : "=r"(a) : "l"(p));
    return a;
}
__device__ __forceinline__ void cpasync16(uint32_t dst, const void* src){
    asm volatile("cp.async.cg.shared.global [%0], [%1], 16;" :: "r"(dst), "l"(src));
}
__device__ __forceinline__ void ldsm4(uint32_t* r, uint32_t addr){
    asm volatile("ldmatrix.sync.aligned.m8n8.x4.shared.b16 {%0,%1,%2,%3}, [%4];"
        : "=r"(r[0]), "=r"(r[1]), "=r"(r[2]), "=r"(r[3]) : "r"(addr));
}
__device__ __forceinline__ void mma_hf(float* c, const uint32_t* a, const uint32_t* b){
    asm volatile("mma.sync.aligned.m16n8k16.row.col.f32.f16.f16.f32 "
        "{%0,%1,%2,%3},{%4,%5,%6,%7},{%8,%9},{%0,%1,%2,%3};"
        : "+f"(c[0]), "+f"(c[1]), "+f"(c[2]), "+f"(c[3])
        : "r"(a[0]), "r"(a[1]), "r"(a[2]), "r"(a[3]), "r"(b[0]), "r"(b[1]));
}
__device__ __forceinline__ uint32_t pack_h2(float x, float y){
    __half2 t = __floats2half2_rn(x, y);
    return *reinterpret_cast<uint32_t*>(&t);
}

#define PITCH 80

// ======================= fp16 GEMM =======================
// D[m][n] = sum_k A[m][k]*B[n][k] (+bias). CTA 128x256, Kc=32, 8 warps, 4-stage.
#define HF_OFF_A  0u
#define HF_OFF_B  10240u
#define HF_STAGE  30720u
#define HF_NSTAGE 4
#define HF_SMEM (HF_NSTAGE*HF_STAGE)

__device__ __forceinline__ void hf_load_stage(uint32_t sb, int stage,
    const __half* __restrict__ A, const __half* __restrict__ Bm,
    int lda, int ldb, int m0, int n0, int k0, int tid)
{
    uint32_t st = sb + (uint32_t)stage * HF_STAGE;
    #pragma unroll
    for (int it = 0; it < 6; it++) {
        int g = tid + it * 256;
        const __half* src;
        uint32_t dst;
        if (g < 512) {
            int r = g >> 2, q = g & 3;
            src = A + (long long)(m0 + r) * lda + k0 + q * 8;
            dst = st + HF_OFF_A + (uint32_t)(r * PITCH + q * 16);
        } else {
            int gb = g - 512;
            int r = gb >> 2, q = gb & 3;
            src = Bm + (long long)(n0 + r) * ldb + k0 + q * 8;
            dst = st + HF_OFF_B + (uint32_t)(r * PITCH + q * 16);
        }
        cpasync16(dst, src);
    }
}

__device__ __forceinline__ void hf_compute(uint32_t sb, int stage,
                                           int wm, int wn, int lane,
                                           float acc[2][16][4])
{
    uint32_t st = sb + (uint32_t)stage * HF_STAGE;
    uint32_t aBase = st + HF_OFF_A + (uint32_t)(wm * 32) * PITCH;
    uint32_t bBase = st + HF_OFF_B + (uint32_t)(wn * 128) * PITCH;
    int l15 = lane & 15;
    int lh = lane >> 4;
    int bn_off = ((lane >> 4) & 1) * 8 + (lane & 7);
    int bhalf = (lane >> 3) & 1;

    #pragma unroll
    for (int s = 0; s < 2; s++) {
        uint32_t aoff = (uint32_t)(s * 32 + lh * 16);
        uint32_t aF[2][4];
        ldsm4(aF[0], aBase + (uint32_t)(l15) * PITCH + aoff);
        ldsm4(aF[1], aBase + (uint32_t)(16 + l15) * PITCH + aoff);

        #pragma unroll
        for (int h = 0; h < 2; h++) {
            uint32_t bF[8][2];
            #pragma unroll
            for (int p = 0; p < 4; p++) {
                uint32_t addr = (uint32_t)(((h * 4 + p) * 16 + bn_off) * PITCH + s * 32 + bhalf * 16);
                uint32_t r4[4];
                ldsm4(r4, bBase + addr);
                bF[2*p][0] = r4[0]; bF[2*p][1] = r4[1];
                bF[2*p+1][0] = r4[2]; bF[2*p+1][1] = r4[3];
            }
            #pragma unroll
            for (int mt = 0; mt < 2; mt++)
                #pragma unroll
                for (int nt = 0; nt < 8; nt++)
                    mma_hf(acc[mt][h*8+nt], aF[mt], bF[nt]);
        }
    }
}

// OUTMODE 0: fp32 to Cf ; 1: fp16 to Ch
// bias_mode: 0 none, 1 row bias, 2 col bias, 3 per-z col bias (bias[z*zstride+col])
template<int OUTMODE>
__global__ void __launch_bounds__(256, 1)
gemm_hf(const __half* __restrict__ A, long long a_bs, int lda,
        const __half* __restrict__ Bm, long long b_bs, int ldb,
        float* __restrict__ Cf, __half* __restrict__ Ch,
        long long c_bs, int ldc,
        int K, const float* __restrict__ bias, int bias_mode, long long zstride)
{
    extern __shared__ char sm[];
    uint32_t sb = smem_u32(sm);
    int tid = threadIdx.x;
    int wid = tid >> 5, lane = tid & 31;
    int wm = wid & 3, wn = wid >> 2;
    int z = blockIdx.z;
    int m0 = blockIdx.y * 128;
    int n0 = blockIdx.x * 256;

    const __half* pA = A + (long long)z * a_bs;
    const __half* pB = Bm + (long long)z * b_bs;

    float acc[2][16][4] = {};
    int nc = K / 32;

    #pragma unroll
    for (int s = 0; s < 3; s++) {
        if (s < nc)
            hf_load_stage(sb, s, pA, pB, lda, ldb, m0, n0, s * 32, tid);
        asm volatile("cp.async.commit_group;" ::: "memory");
    }

    for (int i = 0; i < nc; i++) {
        asm volatile("cp.async.wait_group 2;" ::: "memory");
        __syncthreads();
        if (i + 3 < nc)
            hf_load_stage(sb, (i + 3) & (HF_NSTAGE - 1), pA, pB, lda, ldb, m0, n0, (i + 3) * 32, tid);
        asm volatile("cp.async.commit_group;" ::: "memory");
        hf_compute(sb, i & (HF_NSTAGE - 1), wm, wn, lane, acc);
    }

    int r = lane >> 2, cg = lane & 3;
    int mb = m0 + wm * 32, nb = n0 + wn * 128;
    const float* zb = bias + (bias_mode == 3 ? (long long)z * zstride : 0);
    #pragma unroll
    for (int mt = 0; mt < 2; mt++) {
        int mrow = mb + mt * 16 + r;
        float br0 = 0.0f, br1 = 0.0f;
        if (bias_mode == 1) { br0 = __ldg(&bias[mrow]); br1 = __ldg(&bias[mrow + 8]); }
        #pragma unroll
        for (int nt = 0; nt < 16; nt++) {
            int col = nb + nt * 8 + cg * 2;
            float bc0 = 0.0f, bc1 = 0.0f;
            if (bias_mode >= 2) { bc0 = __ldg(&zb[col]); bc1 = __ldg(&zb[col + 1]); }
            float v00 = acc[mt][nt][0] + br0 + bc0;
            float v01 = acc[mt][nt][1] + br0 + bc1;
            float v10 = acc[mt][nt][2] + br1 + bc0;
            float v11 = acc[mt][nt][3] + br1 + bc1;
            long long o0 = (long long)z * c_bs + (long long)mrow * ldc + col;
            long long o1 = o0 + (long long)8 * ldc;
            if (OUTMODE == 0) {
                *reinterpret_cast<float2*>(Cf + o0) = make_float2(v00, v01);
                *reinterpret_cast<float2*>(Cf + o1) = make_float2(v10, v11);
            } else {
                *reinterpret_cast<uint32_t*>(Ch + o0) = pack_h2(v00, v01);
                *reinterpret_cast<uint32_t*>(Ch + o1) = pack_h2(v10, v11);
            }
        }
    }
}

// ======================= conversions =======================
__global__ void convert_h_kernel(const float* __restrict__ src, __half* __restrict__ dst, int n) {
    int i = blockIdx.x * blockDim.x + threadIdx.x;
    if (i < n) dst[i] = __float2half_rn(src[i]);
}

// src [z][R][CC] -> dst [z][CC][R] fp16
__global__ void transpose_convert_kernel(const float* __restrict__ src,
                                         __half* __restrict__ dst, int R, int CC) {
    __shared__ float tile[32][33];
    int z = blockIdx.z;
    int c0 = blockIdx.x * 32;
    int r0 = blockIdx.y * 32;
    int tx = threadIdx.x, ty = threadIdx.y;
    const float* s = src + (long long)z * R * CC;
    #pragma unroll
    for (int i = 0; i < 4; i++)
        tile[ty + i * 8][tx] = s[(long long)(r0 + ty + i * 8) * CC + c0 + tx];
    __syncthreads();
    __half* o = dst + (long long)z * R * CC;
    #pragma unroll
    for (int i = 0; i < 4; i++)
        o[(long long)(c0 + ty + i * 8) * R + r0 + tx] = __float2half_rn(tile[tx][ty + i * 8]);
}

// x [z][C][64x64] -> pooled transposed fp16 [z][m][c]
__global__ void pool_transpose_kernel(const float* __restrict__ x, __half* __restrict__ dst) {
    __shared__ float tile[32][33];
    int z = blockIdx.z;
    int m0 = blockIdx.x * 32;
    int c0 = blockIdx.y * 32;
    int tx = threadIdx.x, ty = threadIdx.y;
    #pragma unroll
    for (int i = 0; i < 4; i++) {
        int c = c0 + ty + i * 8;
        int m = m0 + tx;
        int pi = m >> 5, pj = m & 31;
        const float* b = x + ((long long)z * C_ + c) * 4096 + (pi * 2) * 64 + pj * 2;
        tile[ty + i * 8][tx] = fmaxf(fmaxf(b[0], b[1]), fmaxf(b[64], b[65]));
    }
    __syncthreads();
    #pragma unroll
    for (int i = 0; i < 4; i++)
        dst[((long long)z * M_ + m0 + ty + i * 8) * C_ + c0 + tx] =
            __float2half_rn(tile[tx][ty + i * 8]);
}

// ======================= g centering: gf [z*CI rows][M] -> gmean + gdev fp16 ===========
__global__ void gcenter_kernel(const float* __restrict__ gf, float* __restrict__ gmean,
                               __half* __restrict__ gdev) {
    int row = blockIdx.x;                  // 0 .. B*CI-1
    const float* r = gf + (size_t)row * M_;
    int tid = threadIdx.x;                 // 256
    float v[4];
    float s = 0.0f;
    #pragma unroll
    for (int i = 0; i < 4; i++) { v[i] = r[tid + 256 * i]; s += v[i]; }
    __shared__ float red[8];
    #pragma unroll
    for (int o = 16; o > 0; o >>= 1) s += __shfl_xor_sync(0xffffffffu, s, o);
    if ((tid & 31) == 0) red[tid >> 5] = s;
    __syncthreads();
    float tot = (red[0] + red[1]) + (red[2] + red[3]) + (red[4] + red[5]) + (red[6] + red[7]);
    float mean = tot * (1.0f / M_);
    if (tid == 0) gmean[row] = mean;
    __half* o = gdev + (size_t)row * M_;
    #pragma unroll
    for (int i = 0; i < 4; i++)
        o[tid + 256 * i] = __float2half_rn(v[i] - mean);
}

// ======================= softmax (scaled) -> fp16 =======================
__global__ void softmax_kernel(const float* __restrict__ s, __half* __restrict__ p, float scale) {
    const float* row = s + (size_t)blockIdx.x * M_;
    int tid = threadIdx.x;
    float v[4];
    float mx = -1e30f;
    #pragma unroll
    for (int i = 0; i < 4; i++) { v[i] = row[tid + 256 * i] * scale; mx = fmaxf(mx, v[i]); }
    __shared__ float red[8], red2[8];
    #pragma unroll
    for (int o = 16; o > 0; o >>= 1) mx = fmaxf(mx, __shfl_xor_sync(0xffffffffu, mx, o));
    if ((tid & 31) == 0) red[tid >> 5] = mx;
    __syncthreads();
    mx = fmaxf(fmaxf(fmaxf(red[0], red[1]), fmaxf(red[2], red[3])),
               fmaxf(fmaxf(red[4], red[5]), fmaxf(red[6], red[7])));
    float sum = 0.0f;
    #pragma unroll
    for (int i = 0; i < 4; i++) { v[i] = __expf(v[i] - mx); sum += v[i]; }
    #pragma unroll
    for (int o = 16; o > 0; o >>= 1) sum += __shfl_xor_sync(0xffffffffu, sum, o);
    if ((tid & 31) == 0) red2[tid >> 5] = sum;
    __syncthreads();
    sum = (red2[0] + red2[1]) + (red2[2] + red2[3]) + (red2[4] + red2[5]) + (red2[6] + red2[7]);
    float inv = 1.0f / sum;
    size_t base = (size_t)blockIdx.x * M_;
    #pragma unroll
    for (int i = 0; i < 4; i++)
        p[base + tid + 256 * i] = __float2half_rn(v[i] * inv);
}

// ======================= t centering =======================
__global__ void zero_f_kernel(float* p, int n) {
    int i = blockIdx.x * blockDim.x + threadIdx.x;
    if (i < n) p[i] = 0.0f;
}
// t [z][n][ci]; partial col-sums over n -> tmean (atomic)
__global__ void tmean_kernel(const float* __restrict__ t, float* __restrict__ tmean) {
    int ci = blockIdx.x * 128 + threadIdx.x;
    int z = blockIdx.y;
    int n0 = blockIdx.z * 512;
    const float* base = t + ((long long)z * N_ + n0) * CI_ + ci;
    float s = 0.0f;
    for (int r = 0; r < 512; r++)
        s += base[(long long)r * CI_];
    atomicAdd(&tmean[z * CI_ + ci], s * (1.0f / N_));
}
__global__ void tdev_kernel(const float* __restrict__ t, const float* __restrict__ tmean,
                            __half* __restrict__ tdev) {
    long long idx = (long long)blockIdx.x * blockDim.x + threadIdx.x;
    if (idx >= (long long)B_ * N_ * CI_) return;
    int ci = (int)(idx & (CI_ - 1));
    int z = (int)(idx >> 21);              // N_*CI_ = 2^21
    tdev[idx] = __float2half_rn(t[idx] - tmean[z * CI_ + ci]);
}
// ymean[z][c] = b_out[c] + sum_ci w_out[c][ci] * tmean[z][ci]   (fp32 exact)
__global__ void ymean_kernel(const float* __restrict__ w_out, const float* __restrict__ b_out,
                             const float* __restrict__ tmean, float* __restrict__ ymean) {
    int c = blockIdx.x * 256 + threadIdx.x;
    int z = blockIdx.y;
    const float* w = w_out + (long long)c * CI_;
    const float* tm = tmean + z * CI_;
    float s = b_out[c];
    #pragma unroll 4
    for (int ci = 0; ci < CI_; ci++)
        s += w[ci] * tm[ci];
    ymean[z * C_ + c] = s;
}

// ======================= BatchNorm =======================
__global__ void bn_zero_kernel(double* sums) {
    int i = blockIdx.x * blockDim.x + threadIdx.x;
    if (i < 2 * C_) sums[i] = 0.0;
}
__global__ void bn_stats_kernel(const float* __restrict__ yT, double* __restrict__ sums) {
    int tid = threadIdx.x;
    int c = blockIdx.x * 128 + (tid & 127);
    int half_ = tid >> 7;
    int r0 = blockIdx.y * 1024 + half_ * 512;
    float s = 0.0f, s2 = 0.0f;
    for (int r = 0; r < 512; r++) {
        float v = yT[(long long)(r0 + r) * C_ + c];
        s += v; s2 += v * v;
    }
    atomicAdd(&sums[c], (double)s);
    atomicAdd(&sums[C_ + c], (double)s2);
}
__global__ void bn_final_kernel(const double* __restrict__ sums, float* __restrict__ stat) {
    int c = blockIdx.x * blockDim.x + threadIdx.x;
    if (c < C_) {
        double cnt = (double)B_ * N_;
        double mean = sums[c] / cnt;
        double var = sums[C_ + c] / cnt - mean * mean;
        stat[c] = (float)mean;
        stat[C_ + c] = rsqrtf((float)var + 1e-5f);
    }
}
__global__ void bn_apply_kernel(const float* __restrict__ yT, const float* __restrict__ x,
                                const float* __restrict__ stat,
                                const float* __restrict__ gamma, const float* __restrict__ beta,
                                float* __restrict__ out) {
    __shared__ float tile[32][33];
    int z = blockIdx.z;
    int n0 = blockIdx.x * 32;
    int c0 = blockIdx.y * 32;
    int tx = threadIdx.x, ty = threadIdx.y;
    #pragma unroll
    for (int i = 0; i < 4; i++)
        tile[ty + i * 8][tx] = yT[((long long)z * N_ + n0 + ty + i * 8) * C_ + c0 + tx];
    __syncthreads();
    #pragma unroll
    for (int i = 0; i < 4; i++) {
        int c = c0 + ty + i * 8;
        int n = n0 + tx;
        float mean = stat[c], rstd = stat[C_ + c];
        long long o = ((long long)z * C_ + c) * N_ + n;
        out[o] = (tile[tx][ty + i * 8] - mean) * rstd * gamma[c] + beta[c] + x[o];
    }
}

// ======================= launch =======================
extern "C" void kernel_launch(void* const* d_in, const int* in_sizes, int n_in,
                              void* d_out, int out_size) {
    const float* x       = (const float*)d_in[0];
    const float* w_theta = (const float*)d_in[1];
    const float* b_theta = (const float*)d_in[2];
    const float* w_phi   = (const float*)d_in[3];
    const float* b_phi   = (const float*)d_in[4];
    const float* w_g     = (const float*)d_in[5];
    const float* b_g     = (const float*)d_in[6];
    const float* w_out   = (const float*)d_in[7];
    const float* b_out   = (const float*)d_in[8];
    const float* gamma   = (const float*)d_in[9];
    const float* beta    = (const float*)d_in[10];
    float* out = (float*)d_out;

    cudaFuncSetAttribute(gemm_hf<0>, cudaFuncAttributeMaxDynamicSharedMemorySize, HF_SMEM);
    cudaFuncSetAttribute(gemm_hf<1>, cudaFuncAttributeMaxDynamicSharedMemorySize, HF_SMEM);

    __half *xT, *pxT, *wth, *wph, *wg, *wo, *thT, *phT, *gdev, *p, *tdev;
    float *gf, *gmean, *scores, *t, *tmean, *ymean, *yT, *bnstat;
    double *bnsum;
    cudaGetSymbolAddress((void**)&xT, s_xT);
    cudaGetSymbolAddress((void**)&pxT, s_pxT);
    cudaGetSymbolAddress((void**)&wth, s_wth);
    cudaGetSymbolAddress((void**)&wph, s_wph);
    cudaGetSymbolAddress((void**)&wg, s_wg);
    cudaGetSymbolAddress((void**)&wo, s_wo);
    cudaGetSymbolAddress((void**)&thT, s_thT);
    cudaGetSymbolAddress((void**)&phT, s_phT);
    cudaGetSymbolAddress((void**)&gf, s_gf);
    cudaGetSymbolAddress((void**)&gdev, s_gdev);
    cudaGetSymbolAddress((void**)&gmean, s_gmean);
    cudaGetSymbolAddress((void**)&scores, s_scores);
    cudaGetSymbolAddress((void**)&p, s_p);
    cudaGetSymbolAddress((void**)&t, s_t);
    cudaGetSymbolAddress((void**)&tdev, s_tdev);
    cudaGetSymbolAddress((void**)&tmean, s_tmean);
    cudaGetSymbolAddress((void**)&ymean, s_ymean);
    cudaGetSymbolAddress((void**)&yT, s_yT);
    cudaGetSymbolAddress((void**)&bnsum, s_bnsum);
    cudaGetSymbolAddress((void**)&bnstat, s_bnstat);

    dim3 tb(32, 8);

    convert_h_kernel<<<(CI_ * C_ + 255) / 256, 256>>>(w_theta, wth, CI_ * C_);
    convert_h_kernel<<<(CI_ * C_ + 255) / 256, 256>>>(w_phi, wph, CI_ * C_);
    convert_h_kernel<<<(CI_ * C_ + 255) / 256, 256>>>(w_g, wg, CI_ * C_);
    convert_h_kernel<<<(C_ * CI_ + 255) / 256, 256>>>(w_out, wo, C_ * CI_);

    transpose_convert_kernel<<<dim3(N_ / 32, C_ / 32, B_), tb>>>(x, xT, C_, N_);
    pool_transpose_kernel<<<dim3(M_ / 32, C_ / 32, B_), tb>>>(x, pxT);

    // GEMM1 (fp16): thT[n][ci] = xT @ w_theta^T ; rows=4096, cols=512, K=1024
    gemm_hf<1><<<dim3(CI_ / 256, N_ / 128, B_), 256, HF_SMEM>>>(
        xT, (long long)N_ * C_, C_,
        wth, 0, C_,
        nullptr, thT, (long long)N_ * CI_, CI_,
        C_, b_theta, 2, 0);
    // GEMM2 (fp16): phT[m][ci] ; rows=1024, cols=512, K=1024
    gemm_hf<1><<<dim3(CI_ / 256, M_ / 128, B_), 256, HF_SMEM>>>(
        pxT, (long long)M_ * C_, C_,
        wph, 0, C_,
        nullptr, phT, (long long)M_ * CI_, CI_,
        C_, b_phi, 2, 0);
    // GEMM3 (fp16 -> fp32): g[ci][m] ; rows=512, cols=1024, K=1024
    gemm_hf<0><<<dim3(M_ / 256, CI_ / 128, B_), 256, HF_SMEM>>>(
        wg, 0, C_,
        pxT, (long long)M_ * C_, C_,
        gf, nullptr, (long long)CI_ * M_, M_,
        C_, b_g, 1, 0);
    // center g
    gcenter_kernel<<<B_ * CI_, 256>>>(gf, gmean, gdev);
    // GEMM4 (fp16): scores[n][m] ; rows=4096, cols=1024, K=512
    gemm_hf<0><<<dim3(M_ / 256, N_ / 128, B_), 256, HF_SMEM>>>(
        thT, (long long)N_ * CI_, CI_,
        phT, (long long)M_ * CI_, CI_,
        scores, nullptr, (long long)N_ * M_, M_,
        CI_, nullptr, 0, 0);
    softmax_kernel<<<B_ * N_, 256>>>(scores, p, rsqrtf((float)CI_));
    // GEMM5 (fp16, centered): t[n][ci] = p @ gdev^T + gmean ; rows=4096, cols=512, K=1024
    gemm_hf<0><<<dim3(CI_ / 256, N_ / 128, B_), 256, HF_SMEM>>>(
        p, (long long)N_ * M_, M_,
        gdev, (long long)CI_ * M_, M_,
        t, nullptr, (long long)N_ * CI_, CI_,
        M_, gmean, 3, CI_);
    // center t
    zero_f_kernel<<<(B_ * CI_ + 255) / 256, 256>>>(tmean, B_ * CI_);
    tmean_kernel<<<dim3(CI_ / 128, B_, 8), 128>>>(t, tmean);
    tdev_kernel<<<(unsigned)(((long long)B_ * N_ * CI_ + 255) / 256), 256>>>(t, tmean, tdev);
    ymean_kernel<<<dim3(C_ / 256, B_), 256>>>(w_out, b_out, tmean, ymean);
    // GEMM6 (fp16, centered): yT[n][c] = tdev @ w_out^T + ymean ; rows=4096, cols=1024, K=512
    gemm_hf<0><<<dim3(C_ / 256, N_ / 128, B_), 256, HF_SMEM>>>(
        tdev, (long long)N_ * CI_, CI_,
        wo, 0, CI_,
        yT, nullptr, (long long)N_ * C_, C_,
        CI_, ymean, 3, C_);

    bn_zero_kernel<<<8, 256>>>(bnsum);
    bn_stats_kernel<<<dim3(C_ / 128, 32), 256>>>(yT, bnsum);
    bn_final_kernel<<<4, 256>>>(bnsum, bnstat);
    bn_apply_kernel<<<dim3(N_ / 32, C_ / 32, B_), tb>>>(yT, x, bnstat, gamma, beta, out);
}